// round 13
// baseline (speedup 1.0000x reference)
#include <cuda_runtime.h>
#include <cuda_fp16.h>
#include <math.h>
#include <stdint.h>

#define BB 2
#define SS 1024
#define DMODEL 1024
#define HH 16
#define DD 64
#define PP 512               // 2*SPAN
#define BH (BB*HH)
#define INV_SCALE 0.07216878364870323f   // 1/sqrt(192)
#define STAGES 3

// ---------------- scratch (static device memory; no allocs allowed) ----------
__device__ __align__(16) __half g_hsh[BB*SS*DMODEL];     // hs fp16
__device__ __align__(16) __half g_relh[PP*DMODEL];       // rel_embeddings fp16
__device__ __align__(16) __half g_Wth[4u*DMODEL*DMODEL]; // Wq^T..Wo^T fp16
__device__ __align__(16) __half g_Qh[BH*SS*DD];          // [bh][s][64]
__device__ __align__(16) __half g_Kh[BH*SS*DD];
__device__ __align__(16) __half g_Vh[BH*SS*DD];          // head-major
__device__ __align__(16) __half g_Vth[BH*DD*SS];         // [bh][64][s]
__device__ __align__(16) __half g_posKh[HH*PP*DD];       // [h][p][64]
__device__ __align__(16) __half g_posQh[HH*PP*DD];
__device__ float  g_C2P[(size_t)BH*SS*PP];               // [bh][q][p] fp32
__device__ float  g_P2C[(size_t)BH*SS*PP];               // [bh][k][p] fp32
__device__ float  g_S[(size_t)BH*SS*SS];                 // scores fp32
__device__ __align__(16) __half g_Ph[(size_t)BH*SS*SS];  // probs fp16
__device__ __align__(16) __half g_ctxh[BB*SS*DMODEL];    // ctx fp16
__device__ float  g_H[BB*SS*DMODEL];
__device__ int    g_idx[2047];

// ---------------- idx table: clip(bucket(delta)+256, 0, 511) -----------------
__global__ void build_idx_kernel() {
    int t = blockIdx.x * blockDim.x + threadIdx.x;
    if (t >= 2047) return;
    int rel = t - 1023;
    int bucket;
    if (rel > -128 && rel < 128) {
        bucket = rel;
    } else {
        double abs_pos = fabs((double)rel);
        if (abs_pos <= 128.0) {
            bucket = rel;
        } else {
            int sgn = (rel > 0) - (rel < 0);
            double lp = ceil(log(abs_pos / 128.0) / log(511.0 / 128.0) * 127.0) + 128.0;
            bucket = (int)lp * sgn;
        }
    }
    int i1 = bucket + 256;
    i1 = i1 < 0 ? 0 : (i1 > 511 ? 511 : i1);
    g_idx[t] = i1;
}

// ---------------- fp32 -> fp16 elementwise convert ----------------------------
__global__ void to_half_kernel(const float4* __restrict__ in, __half* __restrict__ out, int n4) {
    int i = blockIdx.x * blockDim.x + threadIdx.x;
    if (i >= n4) return;
    float4 v = in[i];
    __half2 a = __floats2half2_rn(v.x, v.y);
    __half2 b = __floats2half2_rn(v.z, v.w);
    uint2 st;
    st.x = *(uint32_t*)&a;
    st.y = *(uint32_t*)&b;
    *(uint2*)(out + 4 * i) = st;
}

__device__ __forceinline__ void mma_f16(float (&d)[4],
                                        uint32_t a0, uint32_t a1, uint32_t a2, uint32_t a3,
                                        uint32_t b0, uint32_t b1) {
    asm volatile(
        "mma.sync.aligned.m16n8k16.row.col.f32.f16.f16.f32 "
        "{%0,%1,%2,%3}, {%4,%5,%6,%7}, {%8,%9}, {%0,%1,%2,%3};\n"
        : "+f"(d[0]), "+f"(d[1]), "+f"(d[2]), "+f"(d[3])
        : "r"(a0), "r"(a1), "r"(a2), "r"(a3), "r"(b0), "r"(b1));
}

__device__ __forceinline__ void cpa16(uint32_t s, const void* g) {
    asm volatile("cp.async.cg.shared.global [%0], [%1], 16;\n" :: "r"(s), "l"(g));
}
#define CP_COMMIT() asm volatile("cp.async.commit_group;\n" ::: "memory")
#define CP_WAIT1()  asm volatile("cp.async.wait_group 1;\n" ::: "memory")

// ============================================================================
// NT fp16 GEMM (f32 accum), 3-stage cp.async, 16B-chunk XOR swizzle, k-tile 64.
//   C[z] = A[z] (BM x K, row-major halves) @ B[z] (N x K row-major halves)^T
// BM = 32*MT.  mods: bit0 -> B index z&15 ; bit1 -> A index z&15
// EPI 1: merged qkv+pos head-major scatter (fp16 out) + bias (z 0..4; hextra = rel fp16)
// EPI 2: +bias+resid (fextra) -> fp32 O
// EPI 3: scores = (QK + c2p + p2c gathers)*scale, masked -> -3e38 (fextra = mask) -> fp32
// EPI 5: merged c2p/p2c -> fp32 (z<32: A@B0->O0 ; z>=32: B1@B2->O1)
// ============================================================================
template<int MT, int BN, int EPI>
__global__ __launch_bounds__(256) void mm_h(
    const __half* __restrict__ A, int lda, long long sAz,
    const __half* __restrict__ B0, const __half* __restrict__ B1, const __half* __restrict__ B2,
    int ldb, long long sBz, int mods,
    void* __restrict__ O0, void* __restrict__ O1, void* __restrict__ O2,
    void* __restrict__ O3, void* __restrict__ O4,
    int ldc, long long sCz, int K,
    const float* __restrict__ bias0, const float* __restrict__ bias1, const float* __restrict__ bias2,
    const float* __restrict__ fextra, const __half* __restrict__ hextra,
    int srows)
{
    constexpr int BM = 32 * MT;
    constexpr int WN8 = BN / 32;
    constexpr int AF = BM * 64;      // halves per A stage
    constexpr int BF = BN * 64;
    extern __shared__ __half hsm[];
    __half* sA = hsm;
    __half* sB = hsm + STAGES * AF;

    const int z = blockIdx.z;
    int zeff = z;
    int srows_ = srows;
    const __half* Bsel = B0; const float* bias = bias0; void* Osel = O0;
    const __half* Asel = A;
    if (EPI == 1) {
        if (z == 1)      { Bsel = B1; bias = bias1; Osel = O1; }
        else if (z == 2) { Bsel = B2; bias = bias2; Osel = O2; }
        else if (z == 3) { Bsel = B1; bias = bias1; Osel = O3; Asel = hextra; srows_ = PP; }
        else if (z == 4) { Bsel = B0; bias = bias0; Osel = O4; Asel = hextra; srows_ = PP; }
        if (z >= 3 && blockIdx.y >= 4) return;
    }
    if (EPI == 5) {
        zeff = z & 31;
        if (z >= 32) { Asel = B1; Bsel = B2; Osel = O1; }
    }
    const __half* Ag = Asel + (size_t)((mods & 2) ? (zeff & 15) : zeff) * sAz;
    const __half* Bg = Bsel + (size_t)(((mods & 1) || EPI == 5) ? (zeff & 15) : zeff) * sBz;

    const int tid = threadIdx.x;
    const int m0 = blockIdx.y * BM, n0 = blockIdx.x * BN;
    const uint32_t sA_u = (uint32_t)__cvta_generic_to_shared(sA);
    const uint32_t sB_u = (uint32_t)__cvta_generic_to_shared(sB);

    const int wid = tid >> 5, lane = tid & 31;
    const int wm = wid & 1, wn = wid >> 1;
    const int r = lane >> 2, cq = lane & 3;

    float acc[MT][WN8][4];
    #pragma unroll
    for (int mt = 0; mt < MT; mt++)
        #pragma unroll
        for (int nt = 0; nt < WN8; nt++)
            #pragma unroll
            for (int q = 0; q < 4; q++) acc[mt][nt][q] = 0.f;

    auto loadStage = [&](int st, int k0) {
        #pragma unroll
        for (int i = 0; i < MT; i++) {          // A: BM rows x 8 chunks of 8 halves
            int id = tid + i * 256;
            int row = id >> 3, c = id & 7;
            uint32_t dst = sA_u + (uint32_t)((st * AF + row * 64 + ((c ^ (row & 7)) << 3)) << 1);
            cpa16(dst, Ag + (size_t)(m0 + row) * lda + k0 + (c << 3));
        }
        #pragma unroll
        for (int i = 0; i < BN / 32; i++) {     // B: BN rows x 8 chunks
            int id = tid + i * 256;
            int row = id >> 3, c = id & 7;
            uint32_t dst = sB_u + (uint32_t)((st * BF + row * 64 + ((c ^ (row & 7)) << 3)) << 1);
            cpa16(dst, Bg + (size_t)(n0 + row) * ldb + k0 + (c << 3));
        }
    };

    const int nk = K >> 6;
    loadStage(0, 0);  CP_COMMIT();
    if (nk > 1) loadStage(1, 64);
    CP_COMMIT();

    for (int it = 0; it < nk; it++) {
        CP_WAIT1();
        __syncthreads();
        int nxt = it + 2;
        if (nxt < nk) loadStage(nxt % STAGES, nxt * 64);
        CP_COMMIT();

        const __half* a = sA + (it % STAGES) * AF;
        const __half* b = sB + (it % STAGES) * BF;
        #pragma unroll
        for (int ks = 0; ks < 4; ks++) {        // 4 x k16
            uint32_t af0[MT], af1[MT], af2[MT], af3[MT];
            #pragma unroll
            for (int mt = 0; mt < MT; mt++) {
                int R = wm * (16 * MT) + mt * 16 + r;
                int r7 = R & 7;
                int lo = ((2 * ks) ^ r7) << 3, hi = ((2 * ks + 1) ^ r7) << 3;
                af0[mt] = *(const uint32_t*)&a[R * 64 + lo + 2 * cq];
                af2[mt] = *(const uint32_t*)&a[R * 64 + hi + 2 * cq];
                af1[mt] = *(const uint32_t*)&a[(R + 8) * 64 + lo + 2 * cq];
                af3[mt] = *(const uint32_t*)&a[(R + 8) * 64 + hi + 2 * cq];
            }
            #pragma unroll
            for (int nt = 0; nt < WN8; nt++) {
                int Nn = wn * WN8 * 8 + nt * 8 + r;
                int n7 = Nn & 7;
                uint32_t b0 = *(const uint32_t*)&b[Nn * 64 + (((2 * ks) ^ n7) << 3) + 2 * cq];
                uint32_t b1 = *(const uint32_t*)&b[Nn * 64 + (((2 * ks + 1) ^ n7) << 3) + 2 * cq];
                #pragma unroll
                for (int mt = 0; mt < MT; mt++)
                    mma_f16(acc[mt][nt], af0[mt], af1[mt], af2[mt], af3[mt], b0, b1);
            }
        }
        __syncthreads();
    }

    // EPI3: stage the 255 idx-table entries this tile needs into smem.
    int* sidx = (int*)hsm;
    if (EPI == 3) {
        int base = m0 - n0 - 127 + 1023;
        if (tid < 255) sidx[tid] = g_idx[base + tid];
        __syncthreads();
    }
    const int doff = (EPI == 3) ? (127 - (m0 - n0)) : 0;

    #pragma unroll
    for (int mt = 0; mt < MT; mt++) {
        #pragma unroll
        for (int e = 0; e < 2; e++) {
            int gm = m0 + wm * (16 * MT) + mt * 16 + r + e * 8;
            #pragma unroll
            for (int nt = 0; nt < WN8; nt++) {
                int gn = n0 + wn * WN8 * 8 + nt * 8 + 2 * cq;
                float v0 = acc[mt][nt][e * 2 + 0];
                float v1 = acc[mt][nt][e * 2 + 1];
                if (EPI == 5) {
                    float* Cz = (float*)Osel + (size_t)zeff * sCz;
                    float2 o = {v0, v1};
                    *(float2*)(Cz + (size_t)gm * ldc + gn) = o;
                } else if (EPI == 1) {
                    int h = gn >> 6, d = gn & 63;
                    int b = gm / srows_, s = gm % srows_;
                    __half2 o = __floats2half2_rn(v0 + bias[gn], v1 + bias[gn + 1]);
                    *(__half2*)((__half*)Osel + ((((size_t)b * HH + h) * srows_ + s) << 6) + d) = o;
                } else if (EPI == 2) {
                    size_t ad = (size_t)gm * ldc + gn;
                    float2 rr = *(const float2*)(fextra + ad);
                    float2 o = {v0 + bias[gn] + rr.x, v1 + bias[gn + 1] + rr.y};
                    *(float2*)((float*)Osel + ad) = o;
                } else if (EPI == 3) {
                    float* Cz = (float*)Osel + (size_t)zeff * sCz;
                    int id0 = sidx[gm - gn + doff];
                    int id1 = sidx[gm - gn - 1 + doff];
                    size_t cb = ((size_t)z * SS + gm) * PP;
                    const int* amr = (const int*)fextra + ((size_t)((z >> 4) * SS + gm)) * SS;
                    int2 mk = *(const int2*)(amr + gn);
                    float o0 = mk.x ? (v0 + g_C2P[cb + id0]
                                       + g_P2C[((size_t)z * SS + gn) * PP + id0]) * INV_SCALE
                                    : -3.0e38f;
                    float o1 = mk.y ? (v1 + g_C2P[cb + id1]
                                       + g_P2C[((size_t)z * SS + gn + 1) * PP + id1]) * INV_SCALE
                                    : -3.0e38f;
                    float2 o = {o0, o1};
                    *(float2*)(Cz + (size_t)gm * ldc + gn) = o;
                }
            }
        }
    }
}

// -------- weight transpose -> fp16: Wth[n][k] = (half)W[k][n] ----------------
__global__ void transpose_w(const float* __restrict__ W0, const float* __restrict__ W1,
                            const float* __restrict__ W2, const float* __restrict__ W3)
{
    __shared__ float t[32][33];
    int zz = blockIdx.z;
    const float* W = zz == 0 ? W0 : zz == 1 ? W1 : zz == 2 ? W2 : W3;
    __half* Tz = g_Wth + (size_t)zz * DMODEL * DMODEL;
    int x = blockIdx.x * 32 + threadIdx.x;
    int y0 = blockIdx.y * 32;
    #pragma unroll
    for (int i = threadIdx.y; i < 32; i += 8)
        t[i][threadIdx.x] = W[(size_t)(y0 + i) * DMODEL + x];
    __syncthreads();
    int xo = blockIdx.y * 32 + threadIdx.x;
    int yo0 = blockIdx.x * 32;
    #pragma unroll
    for (int i = threadIdx.y; i < 32; i += 8)
        Tz[(size_t)(yo0 + i) * DMODEL + xo] = __float2half(t[threadIdx.x][i]);
}

// -------- V transpose per head (fp16): Vth[bh][d][s] = Vh[bh][s][d] ----------
__global__ void transpose_v()
{
    __shared__ __half t[32][33];
    int bh = blockIdx.z;
    int s0 = blockIdx.x * 32, d0 = blockIdx.y * 32;
    const __half* Vi = g_Vh + (size_t)bh * SS * DD;
    __half* Vo = g_Vth + (size_t)bh * DD * SS;
    #pragma unroll
    for (int i = threadIdx.y; i < 32; i += 8)
        t[i][threadIdx.x] = Vi[(size_t)(s0 + i) * DD + d0 + threadIdx.x];
    __syncthreads();
    #pragma unroll
    for (int i = threadIdx.y; i < 32; i += 8)
        Vo[(size_t)(d0 + i) * SS + s0 + threadIdx.x] = t[threadIdx.x][i];
}

// ---------------- maskless softmax: fp32 S in, fp16 probs out ----------------
__global__ __launch_bounds__(256) void softmax_kernel()
{
    __shared__ float redm[8];
    __shared__ float reds[8];
    int row = blockIdx.x;              // bh*S + q
    const float4* srow = (const float4*)(g_S + (size_t)row * SS);
    __half* prow = g_Ph + (size_t)row * SS;
    int t = threadIdx.x, lane = t & 31, wid = t >> 5;
    float4 v = srow[t];
    float mx = fmaxf(fmaxf(v.x, v.y), fmaxf(v.z, v.w));
    #pragma unroll
    for (int o = 16; o; o >>= 1) mx = fmaxf(mx, __shfl_xor_sync(0xffffffffu, mx, o));
    if (lane == 0) redm[wid] = mx;
    __syncthreads();
    mx = redm[0];
    #pragma unroll
    for (int i = 1; i < 8; i++) mx = fmaxf(mx, redm[i]);
    float4 p;
    p.x = v.x < -1.0e37f ? 0.f : __expf(v.x - mx);
    p.y = v.y < -1.0e37f ? 0.f : __expf(v.y - mx);
    p.z = v.z < -1.0e37f ? 0.f : __expf(v.z - mx);
    p.w = v.w < -1.0e37f ? 0.f : __expf(v.w - mx);
    float sm = p.x + p.y + p.z + p.w;
    #pragma unroll
    for (int o = 16; o; o >>= 1) sm += __shfl_xor_sync(0xffffffffu, sm, o);
    if (lane == 0) reds[wid] = sm;
    __syncthreads();
    sm = reds[0];
    #pragma unroll
    for (int i = 1; i < 8; i++) sm += reds[i];
    float inv = sm > 0.f ? 1.f / sm : 0.f;
    __half2 h0 = __floats2half2_rn(p.x * inv, p.y * inv);
    __half2 h1 = __floats2half2_rn(p.z * inv, p.w * inv);
    uint2 st;
    st.x = *(uint32_t*)&h0;
    st.y = *(uint32_t*)&h1;
    *(uint2*)(prow + 4 * t) = st;
}

// ============================================================================
// PV fp16 mma: ctx(fp16) = P(fp16) @ V(fp16) per bh.  Block 64q x 64d.
// ============================================================================
#define PVH_AF 4096
#define PVH_BF 4096
#define PVH_SMEM (STAGES * (PVH_AF + PVH_BF) * 2)   // 49152 B

__global__ __launch_bounds__(256) void pv_h()
{
    extern __shared__ __half hsm[];
    __half* sA = hsm;
    __half* sB = hsm + STAGES * PVH_AF;

    const int bh = blockIdx.z, b = bh >> 4, h = bh & 15;
    const int q0 = blockIdx.y * 64;
    const int tid = threadIdx.x, wid = tid >> 5, lane = tid & 31;
    const int wm = wid & 1, wn = wid >> 1, r = lane >> 2, cq = lane & 3;

    const __half* Pg = g_Ph + (size_t)bh * SS * SS + (size_t)q0 * SS;
    const __half* Vg = g_Vth + (size_t)bh * DD * SS;
    const uint32_t sA_u = (uint32_t)__cvta_generic_to_shared(sA);
    const uint32_t sB_u = (uint32_t)__cvta_generic_to_shared(sB);

    float acc[2][2][4];
    #pragma unroll
    for (int mt = 0; mt < 2; mt++)
        #pragma unroll
        for (int nt = 0; nt < 2; nt++)
            #pragma unroll
            for (int q = 0; q < 4; q++) acc[mt][nt][q] = 0.f;

    auto loadStage = [&](int st, int k0) {
        #pragma unroll
        for (int i = 0; i < 2; i++) {
            int id = tid + i * 256;
            int row = id >> 3, c = id & 7;
            uint32_t dst = sA_u + (uint32_t)((st * PVH_AF + row * 64 + ((c ^ (row & 7)) << 3)) << 1);
            cpa16(dst, Pg + (size_t)row * SS + k0 + (c << 3));
        }
        #pragma unroll
        for (int i = 0; i < 2; i++) {
            int id = tid + i * 256;
            int row = id >> 3, c = id & 7;
            uint32_t dst = sB_u + (uint32_t)((st * PVH_BF + row * 64 + ((c ^ (row & 7)) << 3)) << 1);
            cpa16(dst, Vg + (size_t)row * SS + k0 + (c << 3));
        }
    };

    const int nk = SS / 64;
    loadStage(0, 0);  CP_COMMIT();
    loadStage(1, 64); CP_COMMIT();

    for (int it = 0; it < nk; it++) {
        CP_WAIT1();
        __syncthreads();
        int nxt = it + 2;
        if (nxt < nk) loadStage(nxt % STAGES, nxt * 64);
        CP_COMMIT();

        const __half* a = sA + (it % STAGES) * PVH_AF;
        const __half* bb = sB + (it % STAGES) * PVH_BF;
        #pragma unroll
        for (int ks = 0; ks < 4; ks++) {
            uint32_t af0[2], af1[2], af2[2], af3[2];
            #pragma unroll
            for (int mt = 0; mt < 2; mt++) {
                int R = wm * 32 + mt * 16 + r;
                int r7 = R & 7;
                int lo = ((2 * ks) ^ r7) << 3, hi = ((2 * ks + 1) ^ r7) << 3;
                af0[mt] = *(const uint32_t*)&a[R * 64 + lo + 2 * cq];
                af2[mt] = *(const uint32_t*)&a[R * 64 + hi + 2 * cq];
                af1[mt] = *(const uint32_t*)&a[(R + 8) * 64 + lo + 2 * cq];
                af3[mt] = *(const uint32_t*)&a[(R + 8) * 64 + hi + 2 * cq];
            }
            #pragma unroll
            for (int nt = 0; nt < 2; nt++) {
                int n = wn * 16 + nt * 8 + r;
                int n7 = n & 7;
                uint32_t b0 = *(const uint32_t*)&bb[n * 64 + (((2 * ks) ^ n7) << 3) + 2 * cq];
                uint32_t b1 = *(const uint32_t*)&bb[n * 64 + (((2 * ks + 1) ^ n7) << 3) + 2 * cq];
                #pragma unroll
                for (int mt = 0; mt < 2; mt++)
                    mma_f16(acc[mt][nt], af0[mt], af1[mt], af2[mt], af3[mt], b0, b1);
            }
        }
        __syncthreads();
    }

    // epilogue: write ctx fp16 [B,S,DM]
    #pragma unroll
    for (int mt = 0; mt < 2; mt++) {
        #pragma unroll
        for (int e = 0; e < 2; e++) {
            int gm = q0 + wm * 32 + mt * 16 + r + e * 8;
            #pragma unroll
            for (int nt = 0; nt < 2; nt++) {
                int d = wn * 16 + nt * 8 + 2 * cq;
                __half2 o = __floats2half2_rn(acc[mt][nt][e * 2 + 0], acc[mt][nt][e * 2 + 1]);
                *(__half2*)(g_ctxh + (size_t)(b * SS + gm) * DMODEL + h * DD + d) = o;
            }
        }
    }
}

// ---------------- layernorm of g_H, write to output --------------------------
__global__ __launch_bounds__(256) void ln_kernel(
    const float* __restrict__ lw, const float* __restrict__ lb,
    float* __restrict__ out)
{
    __shared__ float red[256];
    __shared__ float red2[256];
    int r = blockIdx.x, t = threadIdx.x;
    const float* x = g_H + (size_t)r * DMODEL;
    float s = 0.f, s2 = 0.f;
    #pragma unroll
    for (int i = 0; i < 4; i++) {
        float v = x[t + i * 256];
        s += v; s2 += v * v;
    }
    red[t] = s; red2[t] = s2; __syncthreads();
    for (int st = 128; st; st >>= 1) {
        if (t < st) { red[t] += red[t + st]; red2[t] += red2[t + st]; }
        __syncthreads();
    }
    float mu = red[0] * (1.f / DMODEL);
    float var = red2[0] * (1.f / DMODEL) - mu * mu;
    float inv = rsqrtf(var + 1e-7f);
    #pragma unroll
    for (int i = 0; i < 4; i++) {
        int c = t + i * 256;
        out[(size_t)r * DMODEL + c] = (x[c] - mu) * inv * lw[c] + lb[c];
    }
}

// ---------------- launch ------------------------------------------------------
extern "C" void kernel_launch(void* const* d_in, const int* in_sizes, int n_in,
                              void* d_out, int out_size)
{
    const float* hs  = (const float*)d_in[0];
    const float* rel = (const float*)d_in[1];
    const float* Wq  = (const float*)d_in[2];  const float* bq = (const float*)d_in[3];
    const float* Wk  = (const float*)d_in[4];  const float* bk = (const float*)d_in[5];
    const float* Wv  = (const float*)d_in[6];  const float* bv = (const float*)d_in[7];
    const float* Wo  = (const float*)d_in[8];  const float* bo = (const float*)d_in[9];
    const float* lw  = (const float*)d_in[10]; const float* lb = (const float*)d_in[11];
    const int*   am  = (const int*)d_in[12];
    float* out = (float*)d_out;

    __half *HSH_, *RELH_, *WTH_, *QH_, *KH_, *VH_, *PKH_, *PQH_, *CTXH_;
    float *C2P_, *P2C_, *S_, *Hb_;
    cudaGetSymbolAddress((void**)&HSH_,  g_hsh);
    cudaGetSymbolAddress((void**)&RELH_, g_relh);
    cudaGetSymbolAddress((void**)&WTH_,  g_Wth);
    cudaGetSymbolAddress((void**)&QH_,   g_Qh);
    cudaGetSymbolAddress((void**)&KH_,   g_Kh);
    cudaGetSymbolAddress((void**)&VH_,   g_Vh);
    cudaGetSymbolAddress((void**)&PKH_,  g_posKh);
    cudaGetSymbolAddress((void**)&PQH_,  g_posQh);
    cudaGetSymbolAddress((void**)&CTXH_, g_ctxh);
    cudaGetSymbolAddress((void**)&C2P_,  g_C2P);
    cudaGetSymbolAddress((void**)&P2C_,  g_P2C);
    cudaGetSymbolAddress((void**)&S_,    g_S);
    cudaGetSymbolAddress((void**)&Hb_,   g_H);

    __half* WTH0 = WTH_;
    __half* WTH1 = WTH_ + (size_t)1 * DMODEL * DMODEL;
    __half* WTH2 = WTH_ + (size_t)2 * DMODEL * DMODEL;
    __half* WTH3 = WTH_ + (size_t)3 * DMODEL * DMODEL;

    const int SMH4 = STAGES * (128 * 64 + 128 * 64) * 2;   // 98304
    const int SMH2 = STAGES * (64 * 64 + 128 * 64) * 2;    // 73728
    cudaFuncSetAttribute(mm_h<4,128,1>, cudaFuncAttributeMaxDynamicSharedMemorySize, SMH4);
    cudaFuncSetAttribute(mm_h<4,128,5>, cudaFuncAttributeMaxDynamicSharedMemorySize, SMH4);
    cudaFuncSetAttribute(mm_h<4,128,3>, cudaFuncAttributeMaxDynamicSharedMemorySize, SMH4);
    cudaFuncSetAttribute(mm_h<2,128,2>, cudaFuncAttributeMaxDynamicSharedMemorySize, SMH2);
    cudaFuncSetAttribute(pv_h, cudaFuncAttributeMaxDynamicSharedMemorySize, PVH_SMEM);

    build_idx_kernel<<<8, 256>>>();
    to_half_kernel<<<2048, 256>>>((const float4*)hs, HSH_, BB*SS*DMODEL/4);
    to_half_kernel<<<512, 256>>>((const float4*)rel, RELH_, PP*DMODEL/4);
    transpose_w<<<dim3(32, 32, 4), dim3(32, 8)>>>(Wq, Wk, Wv, Wo);

    // QKV + position projections in ONE launch (z 0..4; z>=3 uses rel, y<4)
    mm_h<4,128,1><<<dim3(8,16,5),256,SMH4>>>(
        HSH_,1024,0, WTH0,WTH1,WTH2, 1024,0,0,
        QH_,KH_,VH_,PKH_,PQH_, 0,0, 1024, bq,bk,bv, nullptr, RELH_, SS);
    transpose_v<<<dim3(32, 2, 32), dim3(32, 8)>>>();

    // merged disentangled tables: z<32 -> C2P = Q@posK^T ; z>=32 -> P2C = K@posQ^T
    mm_h<4,128,5><<<dim3(4,8,64),256,SMH4>>>(
        QH_,64,(long long)SS*DD, PKH_,KH_,PQH_, 64,(long long)PP*DD,0,
        C2P_,P2C_,nullptr,nullptr,nullptr, PP,(long long)SS*PP, 64,
        nullptr,nullptr,nullptr, nullptr,nullptr, 0);

    // scores = (Q K^T + c2p + p2c gathers)*scale, masked -> -3e38
    mm_h<4,128,3><<<dim3(8,8,32),256,SMH4>>>(
        QH_,64,(long long)SS*DD, KH_,nullptr,nullptr, 64,(long long)SS*DD,0,
        S_,nullptr,nullptr,nullptr,nullptr, SS,(long long)SS*SS, 64,
        nullptr,nullptr,nullptr, (const float*)am,nullptr, 0);
    softmax_kernel<<<BH*SS, 256>>>();

    // ctx(fp16) = probs(fp16) @ V(fp16)  (64-row tiles -> 512 CTAs)
    pv_h<<<dim3(1, 16, 32), 256, PVH_SMEM>>>();

    // output projection + residual -> fp32 H, then layernorm
    mm_h<2,128,2><<<dim3(8,32,1),256,SMH2>>>(
        CTXH_,1024,0, WTH3,nullptr,nullptr, 1024,0,0,
        Hb_,nullptr,nullptr,nullptr,nullptr, 1024,0, 1024,
        bo,nullptr,nullptr, hs,nullptr, 0);
    ln_kernel<<<BB*SS, 256>>>(lw, lb, out);
}

// round 14
// speedup vs baseline: 1.1478x; 1.1478x over previous
#include <cuda_runtime.h>
#include <cuda_fp16.h>
#include <math.h>
#include <stdint.h>

#define BB 2
#define SS 1024
#define DMODEL 1024
#define HH 16
#define DD 64
#define PP 512               // 2*SPAN
#define BH (BB*HH)
#define INV_SCALE 0.07216878364870323f   // 1/sqrt(192)
#define STAGES 3

// ---------------- scratch (static device memory; no allocs allowed) ----------
__device__ float  g_Q[BH*SS*DD];      // [bh][s][64]
__device__ float  g_K[BH*SS*DD];
__device__ float  g_V[BH*SS*DD];
__device__ __half g_Vth[BH*DD*SS];    // [bh][64][s]  fp16
__device__ float  g_posK[HH*PP*DD];   // [h][p][64]
__device__ float  g_posQ[HH*PP*DD];
__device__ float  g_Wt[4u*DMODEL*DMODEL]; // Wq^T, Wk^T, Wv^T, Wo^T
__device__ __align__(16) __half g_C2Ph[(size_t)BH*SS*PP];   // [bh][q][p] fp16
__device__ __align__(16) __half g_P2Ch[(size_t)BH*SS*PP];   // [bh][k][p] fp16
__device__ float  g_S[(size_t)BH*SS*SS];     // scores fp32
__device__ __align__(16) __half g_Ph[(size_t)BH*SS*SS];     // probs fp16
__device__ float  g_ctx[BB*SS*DMODEL];
__device__ float  g_H[BB*SS*DMODEL];
__device__ int    g_idx[2047];

// ---------------- idx table: clip(bucket(delta)+256, 0, 511) -----------------
__global__ void build_idx_kernel() {
    int t = blockIdx.x * blockDim.x + threadIdx.x;
    if (t >= 2047) return;
    int rel = t - 1023;
    int bucket;
    if (rel > -128 && rel < 128) {
        bucket = rel;
    } else {
        double abs_pos = fabs((double)rel);
        if (abs_pos <= 128.0) {
            bucket = rel;
        } else {
            int sgn = (rel > 0) - (rel < 0);
            double lp = ceil(log(abs_pos / 128.0) / log(511.0 / 128.0) * 127.0) + 128.0;
            bucket = (int)lp * sgn;
        }
    }
    int i1 = bucket + 256;
    i1 = i1 < 0 ? 0 : (i1 > 511 ? 511 : i1);
    g_idx[t] = i1;
}

__device__ __forceinline__ float to_tf32(float x) {
    float y;
    asm("cvt.rna.tf32.f32 %0, %1;" : "=f"(y) : "f"(x));
    return y;
}

__device__ __forceinline__ void mma_tf32(float (&d)[4],
                                         uint32_t a0, uint32_t a1, uint32_t a2, uint32_t a3,
                                         uint32_t b0, uint32_t b1) {
    asm volatile(
        "mma.sync.aligned.m16n8k8.row.col.f32.tf32.tf32.f32 "
        "{%0,%1,%2,%3}, {%4,%5,%6,%7}, {%8,%9}, {%0,%1,%2,%3};\n"
        : "+f"(d[0]), "+f"(d[1]), "+f"(d[2]), "+f"(d[3])
        : "r"(a0), "r"(a1), "r"(a2), "r"(a3), "r"(b0), "r"(b1));
}

__device__ __forceinline__ void mma_f16(float (&d)[4],
                                        uint32_t a0, uint32_t a1, uint32_t a2, uint32_t a3,
                                        uint32_t b0, uint32_t b1) {
    asm volatile(
        "mma.sync.aligned.m16n8k16.row.col.f32.f16.f16.f32 "
        "{%0,%1,%2,%3}, {%4,%5,%6,%7}, {%8,%9}, {%0,%1,%2,%3};\n"
        : "+f"(d[0]), "+f"(d[1]), "+f"(d[2]), "+f"(d[3])
        : "r"(a0), "r"(a1), "r"(a2), "r"(a3), "r"(b0), "r"(b1));
}

__device__ __forceinline__ void cpa16(uint32_t s, const void* g) {
    asm volatile("cp.async.cg.shared.global [%0], [%1], 16;\n" :: "r"(s), "l"(g));
}
#define CP_COMMIT() asm volatile("cp.async.commit_group;\n" ::: "memory")
#define CP_WAIT1()  asm volatile("cp.async.wait_group 1;\n" ::: "memory")

// ============================================================================
// NT tf32 GEMM, 3-stage cp.async pipeline, XOR-swizzled smem.
//   C[z] = A[z] (BM x K tiles, row-major) @ B[z] (N x K row-major)^T + epilogue
// BM = 32*MT.  mods: bit0 -> B index z&15 ; bit1 -> A index z&15
// EPI 1: merged qkv+pos head-major scatter + bias (z 0..4; resid = rel ptr)
// EPI 2: +bias+resid
// EPI 3: scores = (QK + c2p + p2c fp16-gathers)*scale, masked -> -3e38
//        (resid = attention-mask ptr; idx table staged in smem)
// EPI 5: merged c2p/p2c -> fp16 tables (z<32: A@B0->O0 ; z>=32: B1@B2->O1)
// ============================================================================
template<int MT, int BN, int EPI>
__global__ __launch_bounds__(256) void mm_nt(
    const float* __restrict__ A, int lda, long long sAz,
    const float* __restrict__ B0, const float* __restrict__ B1, const float* __restrict__ B2,
    int ldb, long long sBz, int mods,
    void* __restrict__ O0, void* __restrict__ O1, void* __restrict__ O2,
    void* __restrict__ O3, void* __restrict__ O4,
    int ldc, long long sCz, int K,
    const float* __restrict__ bias0, const float* __restrict__ bias1, const float* __restrict__ bias2,
    const float* __restrict__ resid, int srows)
{
    constexpr int BM = 32 * MT;
    constexpr int WN8 = BN / 32;
    constexpr int AF = BM * 32;
    constexpr int BF = BN * 32;
    extern __shared__ float sm[];
    float* sA = sm;
    float* sB = sm + STAGES * AF;

    const int z = blockIdx.z;
    int zeff = z;
    int srows_ = srows;
    const float* Bsel = B0; const float* bias = bias0; void* Osel = O0;
    const float* Asel = A;
    if (EPI == 1) {
        if (z == 1)      { Bsel = B1; bias = bias1; Osel = O1; }
        else if (z == 2) { Bsel = B2; bias = bias2; Osel = O2; }
        else if (z == 3) { Bsel = B1; bias = bias1; Osel = O3; Asel = resid; srows_ = PP; }
        else if (z == 4) { Bsel = B0; bias = bias0; Osel = O4; Asel = resid; srows_ = PP; }
        if (z >= 3 && blockIdx.y >= 4) return;
    }
    if (EPI == 5) {
        zeff = z & 31;
        if (z >= 32) { Asel = B1; Bsel = B2; Osel = O1; }
    }
    const float* Ag = Asel + (size_t)((mods & 2) ? (zeff & 15) : zeff) * sAz;
    const float* Bg = Bsel + (size_t)(((mods & 1) || EPI == 5) ? (zeff & 15) : zeff) * sBz;

    const int tid = threadIdx.x;
    const int m0 = blockIdx.y * BM, n0 = blockIdx.x * BN;
    const uint32_t sA_u = (uint32_t)__cvta_generic_to_shared(sA);
    const uint32_t sB_u = (uint32_t)__cvta_generic_to_shared(sB);

    const int wid = tid >> 5, lane = tid & 31;
    const int wm = wid & 1, wn = wid >> 1;
    const int r = lane >> 2, cq = lane & 3;

    float acc[MT][WN8][4];
    #pragma unroll
    for (int mt = 0; mt < MT; mt++)
        #pragma unroll
        for (int nt = 0; nt < WN8; nt++)
            #pragma unroll
            for (int q = 0; q < 4; q++) acc[mt][nt][q] = 0.f;

    auto loadStage = [&](int st, int k0) {
        #pragma unroll
        for (int i = 0; i < MT; i++) {
            int id = tid + i * 256;
            int row = id >> 3, c = id & 7;
            uint32_t dst = sA_u + (uint32_t)((st * AF + row * 32 + ((c ^ (row & 7)) << 2)) << 2);
            cpa16(dst, Ag + (size_t)(m0 + row) * lda + k0 + (c << 2));
        }
        #pragma unroll
        for (int i = 0; i < BN / 32; i++) {
            int id = tid + i * 256;
            int row = id >> 3, c = id & 7;
            uint32_t dst = sB_u + (uint32_t)((st * BF + row * 32 + ((c ^ (row & 7)) << 2)) << 2);
            cpa16(dst, Bg + (size_t)(n0 + row) * ldb + k0 + (c << 2));
        }
    };

    const int nk = K >> 5;
    loadStage(0, 0);  CP_COMMIT();
    loadStage(1, 32); CP_COMMIT();

    for (int it = 0; it < nk; it++) {
        CP_WAIT1();
        __syncthreads();
        int nxt = it + 2;
        if (nxt < nk) loadStage(nxt % STAGES, nxt * 32);
        CP_COMMIT();

        const float* a = sA + (it % STAGES) * AF;
        const float* b = sB + (it % STAGES) * BF;
        #pragma unroll
        for (int ks = 0; ks < 4; ks++) {
            uint32_t af0[MT], af1[MT], af2[MT], af3[MT];
            #pragma unroll
            for (int mt = 0; mt < MT; mt++) {
                int R = wm * (16 * MT) + mt * 16 + r;
                int r7 = R & 7;
                int lo = ((2 * ks) ^ r7) << 2, hi = ((2 * ks + 1) ^ r7) << 2;
                af0[mt] = __float_as_uint(a[R * 32 + lo + cq]);
                af2[mt] = __float_as_uint(a[R * 32 + hi + cq]);
                af1[mt] = __float_as_uint(a[(R + 8) * 32 + lo + cq]);
                af3[mt] = __float_as_uint(a[(R + 8) * 32 + hi + cq]);
            }
            #pragma unroll
            for (int nt = 0; nt < WN8; nt++) {
                int Nn = wn * WN8 * 8 + nt * 8 + r;
                int n7 = Nn & 7;
                int lo = ((2 * ks) ^ n7) << 2, hi = ((2 * ks + 1) ^ n7) << 2;
                uint32_t b0 = __float_as_uint(b[Nn * 32 + lo + cq]);
                uint32_t b1 = __float_as_uint(b[Nn * 32 + hi + cq]);
                #pragma unroll
                for (int mt = 0; mt < MT; mt++)
                    mma_tf32(acc[mt][nt], af0[mt], af1[mt], af2[mt], af3[mt], b0, b1);
            }
        }
        __syncthreads();
    }

    // EPI3: stage the 255 idx-table entries this tile needs into smem.
    int* sidx = (int*)sm;
    if (EPI == 3) {
        int base = m0 - n0 - 127 + 1023;     // g_idx offset of diag (m0-n0-127)
        if (tid < 255) sidx[tid] = g_idx[base + tid];
        __syncthreads();
    }
    const int doff = (EPI == 3) ? (127 - (m0 - n0)) : 0;

    #pragma unroll
    for (int mt = 0; mt < MT; mt++) {
        #pragma unroll
        for (int e = 0; e < 2; e++) {
            int gm = m0 + wm * (16 * MT) + mt * 16 + r + e * 8;
            #pragma unroll
            for (int nt = 0; nt < WN8; nt++) {
                int gn = n0 + wn * WN8 * 8 + nt * 8 + 2 * cq;
                float v0 = acc[mt][nt][e * 2 + 0];
                float v1 = acc[mt][nt][e * 2 + 1];
                if (EPI == 0) {
                    float* Cz = (float*)Osel + (size_t)zeff * sCz;
                    float2 o = {v0, v1};
                    *(float2*)(Cz + (size_t)gm * ldc + gn) = o;
                } else if (EPI == 5) {
                    __half* Cz = (__half*)Osel + (size_t)zeff * sCz;
                    __half2 o = __floats2half2_rn(v0, v1);
                    *(__half2*)(Cz + (size_t)gm * ldc + gn) = o;
                } else if (EPI == 1) {
                    int h = gn >> 6, d = gn & 63;
                    int b = gm / srows_, s = gm % srows_;
                    float2 o = {v0 + bias[gn], v1 + bias[gn + 1]};
                    *(float2*)((float*)Osel + ((((size_t)b * HH + h) * srows_ + s) << 6) + d) = o;
                } else if (EPI == 2) {
                    size_t ad = (size_t)gm * ldc + gn;
                    float2 rr = *(const float2*)(resid + ad);
                    float2 o = {v0 + bias[gn] + rr.x, v1 + bias[gn + 1] + rr.y};
                    *(float2*)((float*)Osel + ad) = o;
                } else if (EPI == 3) {
                    float* Cz = (float*)Osel + (size_t)zeff * sCz;
                    int id0 = sidx[gm - gn + doff];
                    int id1 = sidx[gm - gn - 1 + doff];
                    size_t cb = ((size_t)z * SS + gm) * PP;
                    const int* amr = (const int*)resid + ((size_t)((z >> 4) * SS + gm)) * SS;
                    int2 mk = *(const int2*)(amr + gn);
                    float o0 = mk.x ? (v0 + __half2float(g_C2Ph[cb + id0])
                                       + __half2float(g_P2Ch[((size_t)z * SS + gn) * PP + id0]))
                                      * INV_SCALE
                                    : -3.0e38f;
                    float o1 = mk.y ? (v1 + __half2float(g_C2Ph[cb + id1])
                                       + __half2float(g_P2Ch[((size_t)z * SS + gn + 1) * PP + id1]))
                                      * INV_SCALE
                                    : -3.0e38f;
                    float2 o = {o0, o1};
                    *(float2*)(Cz + (size_t)gm * ldc + gn) = o;
                }
            }
        }
    }
}

// -------- weight transpose (with tf32 rounding): Wt[n][k] = tf32(W[k][n]) ----
__global__ void transpose_w(const float* __restrict__ W0, const float* __restrict__ W1,
                            const float* __restrict__ W2, const float* __restrict__ W3)
{
    __shared__ float t[32][33];
    int zz = blockIdx.z;
    const float* W = zz == 0 ? W0 : zz == 1 ? W1 : zz == 2 ? W2 : W3;
    float* Tz = g_Wt + (size_t)zz * DMODEL * DMODEL;
    int x = blockIdx.x * 32 + threadIdx.x;
    int y0 = blockIdx.y * 32;
    #pragma unroll
    for (int i = threadIdx.y; i < 32; i += 8)
        t[i][threadIdx.x] = to_tf32(W[(size_t)(y0 + i) * DMODEL + x]);
    __syncthreads();
    int xo = blockIdx.y * 32 + threadIdx.x;
    int yo0 = blockIdx.x * 32;
    #pragma unroll
    for (int i = threadIdx.y; i < 32; i += 8)
        Tz[(size_t)(yo0 + i) * DMODEL + xo] = t[threadIdx.x][i];
}

// -------- V transpose per head -> fp16: Vth[bh][d][s] = (half)V[bh][s][d] ----
__global__ void transpose_v()
{
    __shared__ float t[32][33];
    int bh = blockIdx.z;
    int s0 = blockIdx.x * 32, d0 = blockIdx.y * 32;
    const float* Vi = g_V + (size_t)bh * SS * DD;
    __half* Vo = g_Vth + (size_t)bh * DD * SS;
    #pragma unroll
    for (int i = threadIdx.y; i < 32; i += 8)
        t[i][threadIdx.x] = Vi[(size_t)(s0 + i) * DD + d0 + threadIdx.x];
    __syncthreads();
    #pragma unroll
    for (int i = threadIdx.y; i < 32; i += 8)
        Vo[(size_t)(d0 + i) * SS + s0 + threadIdx.x] = __float2half(t[threadIdx.x][i]);
}

// ---------------- maskless softmax: fp32 S in, fp16 probs out ----------------
__global__ __launch_bounds__(256) void softmax_kernel()
{
    __shared__ float redm[8];
    __shared__ float reds[8];
    int row = blockIdx.x;              // bh*S + q
    const float4* srow = (const float4*)(g_S + (size_t)row * SS);
    __half* prow = g_Ph + (size_t)row * SS;
    int t = threadIdx.x, lane = t & 31, wid = t >> 5;
    float4 v = srow[t];
    float mx = fmaxf(fmaxf(v.x, v.y), fmaxf(v.z, v.w));
    #pragma unroll
    for (int o = 16; o; o >>= 1) mx = fmaxf(mx, __shfl_xor_sync(0xffffffffu, mx, o));
    if (lane == 0) redm[wid] = mx;
    __syncthreads();
    mx = redm[0];
    #pragma unroll
    for (int i = 1; i < 8; i++) mx = fmaxf(mx, redm[i]);
    float4 p;
    p.x = v.x < -1.0e37f ? 0.f : __expf(v.x - mx);
    p.y = v.y < -1.0e37f ? 0.f : __expf(v.y - mx);
    p.z = v.z < -1.0e37f ? 0.f : __expf(v.z - mx);
    p.w = v.w < -1.0e37f ? 0.f : __expf(v.w - mx);
    float sm = p.x + p.y + p.z + p.w;
    #pragma unroll
    for (int o = 16; o; o >>= 1) sm += __shfl_xor_sync(0xffffffffu, sm, o);
    if (lane == 0) reds[wid] = sm;
    __syncthreads();
    sm = reds[0];
    #pragma unroll
    for (int i = 1; i < 8; i++) sm += reds[i];
    float inv = sm > 0.f ? 1.f / sm : 0.f;
    __half2 h0 = __floats2half2_rn(p.x * inv, p.y * inv);
    __half2 h1 = __floats2half2_rn(p.z * inv, p.w * inv);
    uint2 st;
    st.x = *(uint32_t*)&h0;
    st.y = *(uint32_t*)&h1;
    *(uint2*)(prow + 4 * t) = st;
}

// ============================================================================
// PV fp16 mma: ctx = P(fp16) @ V(fp16) per bh.  Block 64q x 64d, k-tile 64.
// 3-stage cp.async, 8-half (16B) chunk XOR swizzle.  Grid (1,16,32) = 512 CTAs.
// ============================================================================
#define PVH_AF 4096          // halves per A stage (64*64)
#define PVH_BF 4096
#define PVH_SMEM (STAGES * (PVH_AF + PVH_BF) * 2)   // 49152 B

__global__ __launch_bounds__(256) void pv_h()
{
    extern __shared__ __half hsm[];
    __half* sA = hsm;
    __half* sB = hsm + STAGES * PVH_AF;

    const int bh = blockIdx.z, b = bh >> 4, h = bh & 15;
    const int q0 = blockIdx.y * 64;
    const int tid = threadIdx.x, wid = tid >> 5, lane = tid & 31;
    const int wm = wid & 1, wn = wid >> 1, r = lane >> 2, cq = lane & 3;

    const __half* Pg = g_Ph + (size_t)bh * SS * SS + (size_t)q0 * SS;
    const __half* Vg = g_Vth + (size_t)bh * DD * SS;
    const uint32_t sA_u = (uint32_t)__cvta_generic_to_shared(sA);
    const uint32_t sB_u = (uint32_t)__cvta_generic_to_shared(sB);

    float acc[2][2][4];
    #pragma unroll
    for (int mt = 0; mt < 2; mt++)
        #pragma unroll
        for (int nt = 0; nt < 2; nt++)
            #pragma unroll
            for (int q = 0; q < 4; q++) acc[mt][nt][q] = 0.f;

    auto loadStage = [&](int st, int k0) {
        #pragma unroll
        for (int i = 0; i < 2; i++) {       // A: 64 rows x 8 chunks of 8 halves
            int id = tid + i * 256;
            int row = id >> 3, c = id & 7;
            uint32_t dst = sA_u + (uint32_t)((st * PVH_AF + row * 64 + ((c ^ (row & 7)) << 3)) << 1);
            cpa16(dst, Pg + (size_t)row * SS + k0 + (c << 3));
        }
        #pragma unroll
        for (int i = 0; i < 2; i++) {       // B: 64 d-rows x 8 chunks
            int id = tid + i * 256;
            int row = id >> 3, c = id & 7;
            uint32_t dst = sB_u + (uint32_t)((st * PVH_BF + row * 64 + ((c ^ (row & 7)) << 3)) << 1);
            cpa16(dst, Vg + (size_t)row * SS + k0 + (c << 3));
        }
    };

    const int nk = SS / 64;
    loadStage(0, 0);  CP_COMMIT();
    loadStage(1, 64); CP_COMMIT();

    for (int it = 0; it < nk; it++) {
        CP_WAIT1();
        __syncthreads();
        int nxt = it + 2;
        if (nxt < nk) loadStage(nxt % STAGES, nxt * 64);
        CP_COMMIT();

        const __half* a = sA + (it % STAGES) * PVH_AF;
        const __half* bb = sB + (it % STAGES) * PVH_BF;
        #pragma unroll
        for (int ks = 0; ks < 4; ks++) {     // 4 x k16
            uint32_t af0[2], af1[2], af2[2], af3[2];
            #pragma unroll
            for (int mt = 0; mt < 2; mt++) {
                int R = wm * 32 + mt * 16 + r;
                int r7 = R & 7;
                int lo = ((2 * ks) ^ r7) << 3, hi = ((2 * ks + 1) ^ r7) << 3;
                af0[mt] = *(const uint32_t*)&a[R * 64 + lo + 2 * cq];
                af2[mt] = *(const uint32_t*)&a[R * 64 + hi + 2 * cq];
                af1[mt] = *(const uint32_t*)&a[(R + 8) * 64 + lo + 2 * cq];
                af3[mt] = *(const uint32_t*)&a[(R + 8) * 64 + hi + 2 * cq];
            }
            #pragma unroll
            for (int nt = 0; nt < 2; nt++) {
                int n = wn * 16 + nt * 8 + r;    // d index
                int n7 = n & 7;
                uint32_t b0 = *(const uint32_t*)&bb[n * 64 + (((2 * ks) ^ n7) << 3) + 2 * cq];
                uint32_t b1 = *(const uint32_t*)&bb[n * 64 + (((2 * ks + 1) ^ n7) << 3) + 2 * cq];
                #pragma unroll
                for (int mt = 0; mt < 2; mt++)
                    mma_f16(acc[mt][nt], af0[mt], af1[mt], af2[mt], af3[mt], b0, b1);
            }
        }
        __syncthreads();
    }

    // epilogue: write ctx fp32 [B,S,DM]
    #pragma unroll
    for (int mt = 0; mt < 2; mt++) {
        #pragma unroll
        for (int e = 0; e < 2; e++) {
            int gm = q0 + wm * 32 + mt * 16 + r + e * 8;
            #pragma unroll
            for (int nt = 0; nt < 2; nt++) {
                int d = wn * 16 + nt * 8 + 2 * cq;
                float2 o = {acc[mt][nt][e * 2 + 0], acc[mt][nt][e * 2 + 1]};
                *(float2*)(g_ctx + (size_t)(b * SS + gm) * DMODEL + h * DD + d) = o;
            }
        }
    }
}

// ---------------- layernorm of g_H, write to output --------------------------
__global__ __launch_bounds__(256) void ln_kernel(
    const float* __restrict__ lw, const float* __restrict__ lb,
    float* __restrict__ out)
{
    __shared__ float red[256];
    __shared__ float red2[256];
    int r = blockIdx.x, t = threadIdx.x;
    const float* x = g_H + (size_t)r * DMODEL;
    float s = 0.f, s2 = 0.f;
    #pragma unroll
    for (int i = 0; i < 4; i++) {
        float v = x[t + i * 256];
        s += v; s2 += v * v;
    }
    red[t] = s; red2[t] = s2; __syncthreads();
    for (int st = 128; st; st >>= 1) {
        if (t < st) { red[t] += red[t + st]; red2[t] += red2[t + st]; }
        __syncthreads();
    }
    float mu = red[0] * (1.f / DMODEL);
    float var = red2[0] * (1.f / DMODEL) - mu * mu;
    float inv = rsqrtf(var + 1e-7f);
    #pragma unroll
    for (int i = 0; i < 4; i++) {
        int c = t + i * 256;
        out[(size_t)r * DMODEL + c] = (x[c] - mu) * inv * lw[c] + lb[c];
    }
}

// ---------------- launch ------------------------------------------------------
extern "C" void kernel_launch(void* const* d_in, const int* in_sizes, int n_in,
                              void* d_out, int out_size)
{
    const float* hs  = (const float*)d_in[0];
    const float* rel = (const float*)d_in[1];
    const float* Wq  = (const float*)d_in[2];  const float* bq = (const float*)d_in[3];
    const float* Wk  = (const float*)d_in[4];  const float* bk = (const float*)d_in[5];
    const float* Wv  = (const float*)d_in[6];  const float* bv = (const float*)d_in[7];
    const float* Wo  = (const float*)d_in[8];  const float* bo = (const float*)d_in[9];
    const float* lw  = (const float*)d_in[10]; const float* lb = (const float*)d_in[11];
    const int*   am  = (const int*)d_in[12];
    float* out = (float*)d_out;

    float *Q_, *K_, *V_, *PK_, *PQ_, *WT_, *S_, *CTX_, *Hb_;
    __half *C2PH_, *P2CH_;
    cudaGetSymbolAddress((void**)&Q_,    g_Q);
    cudaGetSymbolAddress((void**)&K_,    g_K);
    cudaGetSymbolAddress((void**)&V_,    g_V);
    cudaGetSymbolAddress((void**)&PK_,   g_posK);
    cudaGetSymbolAddress((void**)&PQ_,   g_posQ);
    cudaGetSymbolAddress((void**)&WT_,   g_Wt);
    cudaGetSymbolAddress((void**)&C2PH_, g_C2Ph);
    cudaGetSymbolAddress((void**)&P2CH_, g_P2Ch);
    cudaGetSymbolAddress((void**)&S_,    g_S);
    cudaGetSymbolAddress((void**)&CTX_,  g_ctx);
    cudaGetSymbolAddress((void**)&Hb_,   g_H);

    float* WT0 = WT_;
    float* WT1 = WT_ + (size_t)1 * DMODEL * DMODEL;
    float* WT2 = WT_ + (size_t)2 * DMODEL * DMODEL;
    float* WT3 = WT_ + (size_t)3 * DMODEL * DMODEL;

    const int SM4_128 = STAGES * (128 * 32 + 128 * 32) * 4;   // 98304
    const int SM2_128 = STAGES * (64 * 32 + 128 * 32) * 4;    // 73728
    cudaFuncSetAttribute(mm_nt<4,128,1>, cudaFuncAttributeMaxDynamicSharedMemorySize, SM4_128);
    cudaFuncSetAttribute(mm_nt<4,128,5>, cudaFuncAttributeMaxDynamicSharedMemorySize, SM4_128);
    cudaFuncSetAttribute(mm_nt<4,128,3>, cudaFuncAttributeMaxDynamicSharedMemorySize, SM4_128);
    cudaFuncSetAttribute(mm_nt<2,128,2>, cudaFuncAttributeMaxDynamicSharedMemorySize, SM2_128);
    cudaFuncSetAttribute(pv_h, cudaFuncAttributeMaxDynamicSharedMemorySize, PVH_SMEM);

    build_idx_kernel<<<8, 256>>>();
    transpose_w<<<dim3(32, 32, 4), dim3(32, 8)>>>(Wq, Wk, Wv, Wo);

    // QKV + position projections in ONE launch (z 0..4; z>=3 uses rel, y<4)
    mm_nt<4,128,1><<<dim3(8,16,5),256,SM4_128>>>(
        hs,1024,0, WT0,WT1,WT2, 1024,0,0,
        Q_,K_,V_,PK_,PQ_, 0,0, 1024, bq,bk,bv, rel, SS);
    transpose_v<<<dim3(32, 2, 32), dim3(32, 8)>>>();

    // merged disentangled tables (fp16 out): z<32 -> C2P ; z>=32 -> P2C
    mm_nt<4,128,5><<<dim3(4,8,64),256,SM4_128>>>(
        Q_,64,(long long)SS*DD, PK_,K_,PQ_, 64,(long long)PP*DD,0,
        C2PH_,P2CH_,nullptr,nullptr,nullptr, PP,(long long)SS*PP, 64,
        nullptr,nullptr,nullptr, nullptr, 0);

    // scores = (Q K^T + c2p + p2c fp16-gathers)*scale, masked -> -3e38
    mm_nt<4,128,3><<<dim3(8,8,32),256,SM4_128>>>(
        Q_,64,(long long)SS*DD, K_,nullptr,nullptr, 64,(long long)SS*DD,0,
        S_,nullptr,nullptr,nullptr,nullptr, SS,(long long)SS*SS, 64,
        nullptr,nullptr,nullptr, (const float*)am, 0);
    softmax_kernel<<<BH*SS, 256>>>();

    // ctx = probs(fp16) @ V(fp16)  (64-row tiles -> 512 CTAs)
    pv_h<<<dim3(1, 16, 32), 256, PVH_SMEM>>>();

    // output projection + residual (64-row tiles -> 256 CTAs), then layernorm
    mm_nt<2,128,2><<<dim3(8,32,1),256,SM2_128>>>(
        CTX_,1024,0, WT3,nullptr,nullptr, 1024,0,0,
        Hb_,nullptr,nullptr,nullptr,nullptr, 1024,0, 1024,
        bo,nullptr,nullptr, hs, 0);
    ln_kernel<<<BB*SS, 256>>>(lw, lb, out);
}

// round 15
// speedup vs baseline: 1.1587x; 1.0095x over previous
#include <cuda_runtime.h>
#include <cuda_fp16.h>
#include <math.h>
#include <stdint.h>

#define BB 2
#define SS 1024
#define DMODEL 1024
#define HH 16
#define DD 64
#define PP 512               // 2*SPAN
#define BH (BB*HH)
#define INV_SCALE 0.07216878364870323f   // 1/sqrt(192)
#define STAGES 3

// ---------------- scratch (static device memory; no allocs allowed) ----------
__device__ float  g_Q[BH*SS*DD];      // [bh][s][64]
__device__ float  g_K[BH*SS*DD];
__device__ float  g_V[BH*SS*DD];
__device__ __half g_Vth[BH*DD*SS];    // [bh][64][s]  fp16
__device__ float  g_posK[HH*PP*DD];   // [h][p][64]
__device__ float  g_posQ[HH*PP*DD];
__device__ float  g_Wt[4u*DMODEL*DMODEL]; // Wq^T, Wk^T, Wv^T, Wo^T
__device__ __align__(16) __half g_C2Ph[(size_t)BH*SS*PP];   // [bh][q][p] fp16
__device__ __align__(16) __half g_P2Ch[(size_t)BH*SS*PP];   // [bh][k][p] fp16
__device__ __align__(16) __half g_Ph[(size_t)BH*SS*SS];     // scores -> probs, fp16 in place
__device__ float  g_ctx[BB*SS*DMODEL];
__device__ float  g_H[BB*SS*DMODEL];
__device__ int    g_idx[2047];

// ---------------- idx table: clip(bucket(delta)+256, 0, 511) -----------------
__global__ void build_idx_kernel() {
    int t = blockIdx.x * blockDim.x + threadIdx.x;
    if (t >= 2047) return;
    int rel = t - 1023;
    int bucket;
    if (rel > -128 && rel < 128) {
        bucket = rel;
    } else {
        double abs_pos = fabs((double)rel);
        if (abs_pos <= 128.0) {
            bucket = rel;
        } else {
            int sgn = (rel > 0) - (rel < 0);
            double lp = ceil(log(abs_pos / 128.0) / log(511.0 / 128.0) * 127.0) + 128.0;
            bucket = (int)lp * sgn;
        }
    }
    int i1 = bucket + 256;
    i1 = i1 < 0 ? 0 : (i1 > 511 ? 511 : i1);
    g_idx[t] = i1;
}

__device__ __forceinline__ float to_tf32(float x) {
    float y;
    asm("cvt.rna.tf32.f32 %0, %1;" : "=f"(y) : "f"(x));
    return y;
}

__device__ __forceinline__ void mma_tf32(float (&d)[4],
                                         uint32_t a0, uint32_t a1, uint32_t a2, uint32_t a3,
                                         uint32_t b0, uint32_t b1) {
    asm volatile(
        "mma.sync.aligned.m16n8k8.row.col.f32.tf32.tf32.f32 "
        "{%0,%1,%2,%3}, {%4,%5,%6,%7}, {%8,%9}, {%0,%1,%2,%3};\n"
        : "+f"(d[0]), "+f"(d[1]), "+f"(d[2]), "+f"(d[3])
        : "r"(a0), "r"(a1), "r"(a2), "r"(a3), "r"(b0), "r"(b1));
}

__device__ __forceinline__ void mma_f16(float (&d)[4],
                                        uint32_t a0, uint32_t a1, uint32_t a2, uint32_t a3,
                                        uint32_t b0, uint32_t b1) {
    asm volatile(
        "mma.sync.aligned.m16n8k16.row.col.f32.f16.f16.f32 "
        "{%0,%1,%2,%3}, {%4,%5,%6,%7}, {%8,%9}, {%0,%1,%2,%3};\n"
        : "+f"(d[0]), "+f"(d[1]), "+f"(d[2]), "+f"(d[3])
        : "r"(a0), "r"(a1), "r"(a2), "r"(a3), "r"(b0), "r"(b1));
}

__device__ __forceinline__ void cpa16(uint32_t s, const void* g) {
    asm volatile("cp.async.cg.shared.global [%0], [%1], 16;\n" :: "r"(s), "l"(g));
}
#define CP_COMMIT() asm volatile("cp.async.commit_group;\n" ::: "memory")
#define CP_WAIT1()  asm volatile("cp.async.wait_group 1;\n" ::: "memory")

// ============================================================================
// NT tf32 GEMM, 3-stage cp.async pipeline, XOR-swizzled smem.
//   C[z] = A[z] (BM x K tiles, row-major) @ B[z] (N x K row-major)^T + epilogue
// BM = 32*MT.  mods: bit0 -> B index z&15 ; bit1 -> A index z&15
// EPI 1: merged qkv+pos head-major scatter + bias (z 0..4; resid = rel ptr)
// EPI 2: +bias+resid
// EPI 3: scores = (QK + c2p + p2c fp16-gathers)*scale -> fp16 g_Ph,
//        masked -> -60000 (resid = attention-mask ptr; idx table in smem)
// EPI 5: merged c2p/p2c -> fp16 tables (z<32: A@B0->O0 ; z>=32: B1@B2->O1)
// ============================================================================
template<int MT, int BN, int EPI>
__global__ __launch_bounds__(256) void mm_nt(
    const float* __restrict__ A, int lda, long long sAz,
    const float* __restrict__ B0, const float* __restrict__ B1, const float* __restrict__ B2,
    int ldb, long long sBz, int mods,
    void* __restrict__ O0, void* __restrict__ O1, void* __restrict__ O2,
    void* __restrict__ O3, void* __restrict__ O4,
    int ldc, long long sCz, int K,
    const float* __restrict__ bias0, const float* __restrict__ bias1, const float* __restrict__ bias2,
    const float* __restrict__ resid, int srows)
{
    constexpr int BM = 32 * MT;
    constexpr int WN8 = BN / 32;
    constexpr int AF = BM * 32;
    constexpr int BF = BN * 32;
    extern __shared__ float sm[];
    float* sA = sm;
    float* sB = sm + STAGES * AF;

    const int z = blockIdx.z;
    int zeff = z;
    int srows_ = srows;
    const float* Bsel = B0; const float* bias = bias0; void* Osel = O0;
    const float* Asel = A;
    if (EPI == 1) {
        if (z == 1)      { Bsel = B1; bias = bias1; Osel = O1; }
        else if (z == 2) { Bsel = B2; bias = bias2; Osel = O2; }
        else if (z == 3) { Bsel = B1; bias = bias1; Osel = O3; Asel = resid; srows_ = PP; }
        else if (z == 4) { Bsel = B0; bias = bias0; Osel = O4; Asel = resid; srows_ = PP; }
        if (z >= 3 && blockIdx.y >= 4) return;
    }
    if (EPI == 5) {
        zeff = z & 31;
        if (z >= 32) { Asel = B1; Bsel = B2; Osel = O1; }
    }
    const float* Ag = Asel + (size_t)((mods & 2) ? (zeff & 15) : zeff) * sAz;
    const float* Bg = Bsel + (size_t)(((mods & 1) || EPI == 5) ? (zeff & 15) : zeff) * sBz;

    const int tid = threadIdx.x;
    const int m0 = blockIdx.y * BM, n0 = blockIdx.x * BN;
    const uint32_t sA_u = (uint32_t)__cvta_generic_to_shared(sA);
    const uint32_t sB_u = (uint32_t)__cvta_generic_to_shared(sB);

    const int wid = tid >> 5, lane = tid & 31;
    const int wm = wid & 1, wn = wid >> 1;
    const int r = lane >> 2, cq = lane & 3;

    float acc[MT][WN8][4];
    #pragma unroll
    for (int mt = 0; mt < MT; mt++)
        #pragma unroll
        for (int nt = 0; nt < WN8; nt++)
            #pragma unroll
            for (int q = 0; q < 4; q++) acc[mt][nt][q] = 0.f;

    auto loadStage = [&](int st, int k0) {
        #pragma unroll
        for (int i = 0; i < MT; i++) {
            int id = tid + i * 256;
            int row = id >> 3, c = id & 7;
            uint32_t dst = sA_u + (uint32_t)((st * AF + row * 32 + ((c ^ (row & 7)) << 2)) << 2);
            cpa16(dst, Ag + (size_t)(m0 + row) * lda + k0 + (c << 2));
        }
        #pragma unroll
        for (int i = 0; i < BN / 32; i++) {
            int id = tid + i * 256;
            int row = id >> 3, c = id & 7;
            uint32_t dst = sB_u + (uint32_t)((st * BF + row * 32 + ((c ^ (row & 7)) << 2)) << 2);
            cpa16(dst, Bg + (size_t)(n0 + row) * ldb + k0 + (c << 2));
        }
    };

    const int nk = K >> 5;
    loadStage(0, 0);  CP_COMMIT();
    loadStage(1, 32); CP_COMMIT();

    for (int it = 0; it < nk; it++) {
        CP_WAIT1();
        __syncthreads();
        int nxt = it + 2;
        if (nxt < nk) loadStage(nxt % STAGES, nxt * 32);
        CP_COMMIT();

        const float* a = sA + (it % STAGES) * AF;
        const float* b = sB + (it % STAGES) * BF;
        #pragma unroll
        for (int ks = 0; ks < 4; ks++) {
            uint32_t af0[MT], af1[MT], af2[MT], af3[MT];
            #pragma unroll
            for (int mt = 0; mt < MT; mt++) {
                int R = wm * (16 * MT) + mt * 16 + r;
                int r7 = R & 7;
                int lo = ((2 * ks) ^ r7) << 2, hi = ((2 * ks + 1) ^ r7) << 2;
                af0[mt] = __float_as_uint(a[R * 32 + lo + cq]);
                af2[mt] = __float_as_uint(a[R * 32 + hi + cq]);
                af1[mt] = __float_as_uint(a[(R + 8) * 32 + lo + cq]);
                af3[mt] = __float_as_uint(a[(R + 8) * 32 + hi + cq]);
            }
            #pragma unroll
            for (int nt = 0; nt < WN8; nt++) {
                int Nn = wn * WN8 * 8 + nt * 8 + r;
                int n7 = Nn & 7;
                int lo = ((2 * ks) ^ n7) << 2, hi = ((2 * ks + 1) ^ n7) << 2;
                uint32_t b0 = __float_as_uint(b[Nn * 32 + lo + cq]);
                uint32_t b1 = __float_as_uint(b[Nn * 32 + hi + cq]);
                #pragma unroll
                for (int mt = 0; mt < MT; mt++)
                    mma_tf32(acc[mt][nt], af0[mt], af1[mt], af2[mt], af3[mt], b0, b1);
            }
        }
        __syncthreads();
    }

    // EPI3: stage the 255 idx-table entries this tile needs into smem.
    int* sidx = (int*)sm;
    if (EPI == 3) {
        int base = m0 - n0 - 127 + 1023;     // g_idx offset of diag (m0-n0-127)
        if (tid < 255) sidx[tid] = g_idx[base + tid];
        __syncthreads();
    }
    const int doff = (EPI == 3) ? (127 - (m0 - n0)) : 0;

    #pragma unroll
    for (int mt = 0; mt < MT; mt++) {
        #pragma unroll
        for (int e = 0; e < 2; e++) {
            int gm = m0 + wm * (16 * MT) + mt * 16 + r + e * 8;
            #pragma unroll
            for (int nt = 0; nt < WN8; nt++) {
                int gn = n0 + wn * WN8 * 8 + nt * 8 + 2 * cq;
                float v0 = acc[mt][nt][e * 2 + 0];
                float v1 = acc[mt][nt][e * 2 + 1];
                if (EPI == 0) {
                    float* Cz = (float*)Osel + (size_t)zeff * sCz;
                    float2 o = {v0, v1};
                    *(float2*)(Cz + (size_t)gm * ldc + gn) = o;
                } else if (EPI == 5) {
                    __half* Cz = (__half*)Osel + (size_t)zeff * sCz;
                    __half2 o = __floats2half2_rn(v0, v1);
                    *(__half2*)(Cz + (size_t)gm * ldc + gn) = o;
                } else if (EPI == 1) {
                    int h = gn >> 6, d = gn & 63;
                    int b = gm / srows_, s = gm % srows_;
                    float2 o = {v0 + bias[gn], v1 + bias[gn + 1]};
                    *(float2*)((float*)Osel + ((((size_t)b * HH + h) * srows_ + s) << 6) + d) = o;
                } else if (EPI == 2) {
                    size_t ad = (size_t)gm * ldc + gn;
                    float2 rr = *(const float2*)(resid + ad);
                    float2 o = {v0 + bias[gn] + rr.x, v1 + bias[gn + 1] + rr.y};
                    *(float2*)((float*)Osel + ad) = o;
                } else if (EPI == 3) {
                    __half* Cz = (__half*)Osel + (size_t)zeff * sCz;
                    int id0 = sidx[gm - gn + doff];
                    int id1 = sidx[gm - gn - 1 + doff];
                    size_t cb = ((size_t)z * SS + gm) * PP;
                    const int* amr = (const int*)resid + ((size_t)((z >> 4) * SS + gm)) * SS;
                    int2 mk = *(const int2*)(amr + gn);
                    float o0 = mk.x ? (v0 + __half2float(g_C2Ph[cb + id0])
                                       + __half2float(g_P2Ch[((size_t)z * SS + gn) * PP + id0]))
                                      * INV_SCALE
                                    : -60000.0f;
                    float o1 = mk.y ? (v1 + __half2float(g_C2Ph[cb + id1])
                                       + __half2float(g_P2Ch[((size_t)z * SS + gn + 1) * PP + id1]))
                                      * INV_SCALE
                                    : -60000.0f;
                    __half2 o = __floats2half2_rn(o0, o1);
                    *(__half2*)(Cz + (size_t)gm * ldc + gn) = o;
                }
            }
        }
    }
}

// -------- weight transpose (with tf32 rounding): Wt[n][k] = tf32(W[k][n]) ----
__global__ void transpose_w(const float* __restrict__ W0, const float* __restrict__ W1,
                            const float* __restrict__ W2, const float* __restrict__ W3)
{
    __shared__ float t[32][33];
    int zz = blockIdx.z;
    const float* W = zz == 0 ? W0 : zz == 1 ? W1 : zz == 2 ? W2 : W3;
    float* Tz = g_Wt + (size_t)zz * DMODEL * DMODEL;
    int x = blockIdx.x * 32 + threadIdx.x;
    int y0 = blockIdx.y * 32;
    #pragma unroll
    for (int i = threadIdx.y; i < 32; i += 8)
        t[i][threadIdx.x] = to_tf32(W[(size_t)(y0 + i) * DMODEL + x]);
    __syncthreads();
    int xo = blockIdx.y * 32 + threadIdx.x;
    int yo0 = blockIdx.x * 32;
    #pragma unroll
    for (int i = threadIdx.y; i < 32; i += 8)
        Tz[(size_t)(yo0 + i) * DMODEL + xo] = t[threadIdx.x][i];
}

// -------- V transpose per head -> fp16: Vth[bh][d][s] = (half)V[bh][s][d] ----
__global__ void transpose_v()
{
    __shared__ float t[32][33];
    int bh = blockIdx.z;
    int s0 = blockIdx.x * 32, d0 = blockIdx.y * 32;
    const float* Vi = g_V + (size_t)bh * SS * DD;
    __half* Vo = g_Vth + (size_t)bh * DD * SS;
    #pragma unroll
    for (int i = threadIdx.y; i < 32; i += 8)
        t[i][threadIdx.x] = Vi[(size_t)(s0 + i) * DD + d0 + threadIdx.x];
    __syncthreads();
    #pragma unroll
    for (int i = threadIdx.y; i < 32; i += 8)
        Vo[(size_t)(d0 + i) * SS + s0 + threadIdx.x] = __float2half(t[threadIdx.x][i]);
}

// ------- maskless softmax, fp16 in place (sentinel -60000 -> prob 0) ---------
__global__ __launch_bounds__(256) void softmax_kernel()
{
    __shared__ float redm[8];
    __shared__ float reds[8];
    int row = blockIdx.x;              // bh*S + q
    __half* srow = g_Ph + (size_t)row * SS;
    int t = threadIdx.x, lane = t & 31, wid = t >> 5;
    uint2 raw = *(const uint2*)(srow + 4 * t);
    __half2 ha = *(__half2*)&raw.x;
    __half2 hb = *(__half2*)&raw.y;
    float2 f0 = __half22float2(ha);
    float2 f1 = __half22float2(hb);
    float mx = fmaxf(fmaxf(f0.x, f0.y), fmaxf(f1.x, f1.y));
    #pragma unroll
    for (int o = 16; o; o >>= 1) mx = fmaxf(mx, __shfl_xor_sync(0xffffffffu, mx, o));
    if (lane == 0) redm[wid] = mx;
    __syncthreads();
    mx = redm[0];
    #pragma unroll
    for (int i = 1; i < 8; i++) mx = fmaxf(mx, redm[i]);
    float p0 = f0.x < -5.0e4f ? 0.f : __expf(f0.x - mx);
    float p1 = f0.y < -5.0e4f ? 0.f : __expf(f0.y - mx);
    float p2 = f1.x < -5.0e4f ? 0.f : __expf(f1.x - mx);
    float p3 = f1.y < -5.0e4f ? 0.f : __expf(f1.y - mx);
    float sm = p0 + p1 + p2 + p3;
    #pragma unroll
    for (int o = 16; o; o >>= 1) sm += __shfl_xor_sync(0xffffffffu, sm, o);
    if (lane == 0) reds[wid] = sm;
    __syncthreads();
    sm = reds[0];
    #pragma unroll
    for (int i = 1; i < 8; i++) sm += reds[i];
    float inv = sm > 0.f ? 1.f / sm : 0.f;
    __half2 h0 = __floats2half2_rn(p0 * inv, p1 * inv);
    __half2 h1 = __floats2half2_rn(p2 * inv, p3 * inv);
    uint2 st;
    st.x = *(uint32_t*)&h0;
    st.y = *(uint32_t*)&h1;
    *(uint2*)(srow + 4 * t) = st;
}

// ============================================================================
// PV fp16 mma: ctx = P(fp16) @ V(fp16) per bh.  Block 64q x 64d, k-tile 64.
// 3-stage cp.async, 8-half (16B) chunk XOR swizzle.  Grid (1,16,32) = 512 CTAs.
// ============================================================================
#define PVH_AF 4096          // halves per A stage (64*64)
#define PVH_BF 4096
#define PVH_SMEM (STAGES * (PVH_AF + PVH_BF) * 2)   // 49152 B

__global__ __launch_bounds__(256) void pv_h()
{
    extern __shared__ __half hsm[];
    __half* sA = hsm;
    __half* sB = hsm + STAGES * PVH_AF;

    const int bh = blockIdx.z, b = bh >> 4, h = bh & 15;
    const int q0 = blockIdx.y * 64;
    const int tid = threadIdx.x, wid = tid >> 5, lane = tid & 31;
    const int wm = wid & 1, wn = wid >> 1, r = lane >> 2, cq = lane & 3;

    const __half* Pg = g_Ph + (size_t)bh * SS * SS + (size_t)q0 * SS;
    const __half* Vg = g_Vth + (size_t)bh * DD * SS;
    const uint32_t sA_u = (uint32_t)__cvta_generic_to_shared(sA);
    const uint32_t sB_u = (uint32_t)__cvta_generic_to_shared(sB);

    float acc[2][2][4];
    #pragma unroll
    for (int mt = 0; mt < 2; mt++)
        #pragma unroll
        for (int nt = 0; nt < 2; nt++)
            #pragma unroll
            for (int q = 0; q < 4; q++) acc[mt][nt][q] = 0.f;

    auto loadStage = [&](int st, int k0) {
        #pragma unroll
        for (int i = 0; i < 2; i++) {       // A: 64 rows x 8 chunks of 8 halves
            int id = tid + i * 256;
            int row = id >> 3, c = id & 7;
            uint32_t dst = sA_u + (uint32_t)((st * PVH_AF + row * 64 + ((c ^ (row & 7)) << 3)) << 1);
            cpa16(dst, Pg + (size_t)row * SS + k0 + (c << 3));
        }
        #pragma unroll
        for (int i = 0; i < 2; i++) {       // B: 64 d-rows x 8 chunks
            int id = tid + i * 256;
            int row = id >> 3, c = id & 7;
            uint32_t dst = sB_u + (uint32_t)((st * PVH_BF + row * 64 + ((c ^ (row & 7)) << 3)) << 1);
            cpa16(dst, Vg + (size_t)row * SS + k0 + (c << 3));
        }
    };

    const int nk = SS / 64;
    loadStage(0, 0);  CP_COMMIT();
    loadStage(1, 64); CP_COMMIT();

    for (int it = 0; it < nk; it++) {
        CP_WAIT1();
        __syncthreads();
        int nxt = it + 2;
        if (nxt < nk) loadStage(nxt % STAGES, nxt * 64);
        CP_COMMIT();

        const __half* a = sA + (it % STAGES) * PVH_AF;
        const __half* bb = sB + (it % STAGES) * PVH_BF;
        #pragma unroll
        for (int ks = 0; ks < 4; ks++) {     // 4 x k16
            uint32_t af0[2], af1[2], af2[2], af3[2];
            #pragma unroll
            for (int mt = 0; mt < 2; mt++) {
                int R = wm * 32 + mt * 16 + r;
                int r7 = R & 7;
                int lo = ((2 * ks) ^ r7) << 3, hi = ((2 * ks + 1) ^ r7) << 3;
                af0[mt] = *(const uint32_t*)&a[R * 64 + lo + 2 * cq];
                af2[mt] = *(const uint32_t*)&a[R * 64 + hi + 2 * cq];
                af1[mt] = *(const uint32_t*)&a[(R + 8) * 64 + lo + 2 * cq];
                af3[mt] = *(const uint32_t*)&a[(R + 8) * 64 + hi + 2 * cq];
            }
            #pragma unroll
            for (int nt = 0; nt < 2; nt++) {
                int n = wn * 16 + nt * 8 + r;    // d index
                int n7 = n & 7;
                uint32_t b0 = *(const uint32_t*)&bb[n * 64 + (((2 * ks) ^ n7) << 3) + 2 * cq];
                uint32_t b1 = *(const uint32_t*)&bb[n * 64 + (((2 * ks + 1) ^ n7) << 3) + 2 * cq];
                #pragma unroll
                for (int mt = 0; mt < 2; mt++)
                    mma_f16(acc[mt][nt], af0[mt], af1[mt], af2[mt], af3[mt], b0, b1);
            }
        }
        __syncthreads();
    }

    // epilogue: write ctx fp32 [B,S,DM]
    #pragma unroll
    for (int mt = 0; mt < 2; mt++) {
        #pragma unroll
        for (int e = 0; e < 2; e++) {
            int gm = q0 + wm * 32 + mt * 16 + r + e * 8;
            #pragma unroll
            for (int nt = 0; nt < 2; nt++) {
                int d = wn * 16 + nt * 8 + 2 * cq;
                float2 o = {acc[mt][nt][e * 2 + 0], acc[mt][nt][e * 2 + 1]};
                *(float2*)(g_ctx + (size_t)(b * SS + gm) * DMODEL + h * DD + d) = o;
            }
        }
    }
}

// ---------------- layernorm of g_H, write to output --------------------------
__global__ __launch_bounds__(256) void ln_kernel(
    const float* __restrict__ lw, const float* __restrict__ lb,
    float* __restrict__ out)
{
    __shared__ float red[256];
    __shared__ float red2[256];
    int r = blockIdx.x, t = threadIdx.x;
    const float* x = g_H + (size_t)r * DMODEL;
    float s = 0.f, s2 = 0.f;
    #pragma unroll
    for (int i = 0; i < 4; i++) {
        float v = x[t + i * 256];
        s += v; s2 += v * v;
    }
    red[t] = s; red2[t] = s2; __syncthreads();
    for (int st = 128; st; st >>= 1) {
        if (t < st) { red[t] += red[t + st]; red2[t] += red2[t + st]; }
        __syncthreads();
    }
    float mu = red[0] * (1.f / DMODEL);
    float var = red2[0] * (1.f / DMODEL) - mu * mu;
    float inv = rsqrtf(var + 1e-7f);
    #pragma unroll
    for (int i = 0; i < 4; i++) {
        int c = t + i * 256;
        out[(size_t)r * DMODEL + c] = (x[c] - mu) * inv * lw[c] + lb[c];
    }
}

// ---------------- launch ------------------------------------------------------
extern "C" void kernel_launch(void* const* d_in, const int* in_sizes, int n_in,
                              void* d_out, int out_size)
{
    const float* hs  = (const float*)d_in[0];
    const float* rel = (const float*)d_in[1];
    const float* Wq  = (const float*)d_in[2];  const float* bq = (const float*)d_in[3];
    const float* Wk  = (const float*)d_in[4];  const float* bk = (const float*)d_in[5];
    const float* Wv  = (const float*)d_in[6];  const float* bv = (const float*)d_in[7];
    const float* Wo  = (const float*)d_in[8];  const float* bo = (const float*)d_in[9];
    const float* lw  = (const float*)d_in[10]; const float* lb = (const float*)d_in[11];
    const int*   am  = (const int*)d_in[12];
    float* out = (float*)d_out;

    float *Q_, *K_, *V_, *PK_, *PQ_, *WT_, *CTX_, *Hb_;
    __half *C2PH_, *P2CH_, *PH_;
    cudaGetSymbolAddress((void**)&Q_,    g_Q);
    cudaGetSymbolAddress((void**)&K_,    g_K);
    cudaGetSymbolAddress((void**)&V_,    g_V);
    cudaGetSymbolAddress((void**)&PK_,   g_posK);
    cudaGetSymbolAddress((void**)&PQ_,   g_posQ);
    cudaGetSymbolAddress((void**)&WT_,   g_Wt);
    cudaGetSymbolAddress((void**)&C2PH_, g_C2Ph);
    cudaGetSymbolAddress((void**)&P2CH_, g_P2Ch);
    cudaGetSymbolAddress((void**)&PH_,   g_Ph);
    cudaGetSymbolAddress((void**)&CTX_,  g_ctx);
    cudaGetSymbolAddress((void**)&Hb_,   g_H);

    float* WT0 = WT_;
    float* WT1 = WT_ + (size_t)1 * DMODEL * DMODEL;
    float* WT2 = WT_ + (size_t)2 * DMODEL * DMODEL;
    float* WT3 = WT_ + (size_t)3 * DMODEL * DMODEL;

    const int SM4_128 = STAGES * (128 * 32 + 128 * 32) * 4;   // 98304
    const int SM2_128 = STAGES * (64 * 32 + 128 * 32) * 4;    // 73728
    cudaFuncSetAttribute(mm_nt<4,128,1>, cudaFuncAttributeMaxDynamicSharedMemorySize, SM4_128);
    cudaFuncSetAttribute(mm_nt<4,128,5>, cudaFuncAttributeMaxDynamicSharedMemorySize, SM4_128);
    cudaFuncSetAttribute(mm_nt<4,128,3>, cudaFuncAttributeMaxDynamicSharedMemorySize, SM4_128);
    cudaFuncSetAttribute(mm_nt<2,128,2>, cudaFuncAttributeMaxDynamicSharedMemorySize, SM2_128);
    cudaFuncSetAttribute(pv_h, cudaFuncAttributeMaxDynamicSharedMemorySize, PVH_SMEM);

    build_idx_kernel<<<8, 256>>>();
    transpose_w<<<dim3(32, 32, 4), dim3(32, 8)>>>(Wq, Wk, Wv, Wo);

    // QKV + position projections in ONE launch (z 0..4; z>=3 uses rel, y<4)
    mm_nt<4,128,1><<<dim3(8,16,5),256,SM4_128>>>(
        hs,1024,0, WT0,WT1,WT2, 1024,0,0,
        Q_,K_,V_,PK_,PQ_, 0,0, 1024, bq,bk,bv, rel, SS);
    transpose_v<<<dim3(32, 2, 32), dim3(32, 8)>>>();

    // merged disentangled tables (fp16 out): z<32 -> C2P ; z>=32 -> P2C
    mm_nt<4,128,5><<<dim3(4,8,64),256,SM4_128>>>(
        Q_,64,(long long)SS*DD, PK_,K_,PQ_, 64,(long long)PP*DD,0,
        C2PH_,P2CH_,nullptr,nullptr,nullptr, PP,(long long)SS*PP, 64,
        nullptr,nullptr,nullptr, nullptr, 0);

    // scores = (Q K^T + c2p + p2c fp16-gathers)*scale -> fp16, masked -> -60000
    mm_nt<4,128,3><<<dim3(8,8,32),256,SM4_128>>>(
        Q_,64,(long long)SS*DD, K_,nullptr,nullptr, 64,(long long)SS*DD,0,
        PH_,nullptr,nullptr,nullptr,nullptr, SS,(long long)SS*SS, 64,
        nullptr,nullptr,nullptr, (const float*)am, 0);
    softmax_kernel<<<BH*SS, 256>>>();

    // ctx = probs(fp16) @ V(fp16)  (64-row tiles -> 512 CTAs)
    pv_h<<<dim3(1, 16, 32), 256, PVH_SMEM>>>();

    // output projection + residual (64-row tiles -> 256 CTAs), then layernorm
    mm_nt<2,128,2><<<dim3(8,32,1),256,SM2_128>>>(
        CTX_,1024,0, WT3,nullptr,nullptr, 1024,0,0,
        Hb_,nullptr,nullptr,nullptr,nullptr, 1024,0, 1024,
        bo,nullptr,nullptr, hs, 0);
    ln_kernel<<<BB*SS, 256>>>(lw, lb, out);
}

// round 16
// speedup vs baseline: 1.3396x; 1.1561x over previous
#include <cuda_runtime.h>
#include <cuda_fp16.h>
#include <math.h>
#include <stdint.h>

#define BB 2
#define SS 1024
#define DMODEL 1024
#define HH 16
#define DD 64
#define PP 512               // 2*SPAN
#define BH (BB*HH)
#define INV_SCALE 0.07216878364870323f   // 1/sqrt(192)
#define STAGES 3

// ---------------- scratch (static device memory; no allocs allowed) ----------
__device__ __align__(16) __half g_hsh[BB*SS*DMODEL];     // hs fp16
__device__ __align__(16) __half g_relh[PP*DMODEL];       // rel fp16
__device__ __align__(16) __half g_Wth[4u*DMODEL*DMODEL]; // Wq^T..Wo^T fp16
__device__ float  g_Q[BH*SS*DD];      // [bh][s][64] fp32
__device__ float  g_K[BH*SS*DD];
__device__ float  g_V[BH*SS*DD];
__device__ __half g_Vth[BH*DD*SS];    // [bh][64][s] fp16
__device__ float  g_posK[HH*PP*DD];   // [h][p][64] fp32
__device__ float  g_posQ[HH*PP*DD];
__device__ __align__(16) __half g_C2Ph[(size_t)BH*SS*PP];   // [bh][q][p] fp16
__device__ __align__(16) __half g_P2Ch[(size_t)BH*SS*PP];   // [bh][k][p] fp16
__device__ __align__(16) __half g_Ph[(size_t)BH*SS*SS];     // scores->probs fp16
__device__ __align__(16) __half g_ctxh[BB*SS*DMODEL];       // ctx fp16
__device__ float  g_H[BB*SS*DMODEL];
__device__ int    g_idx[2047];

// ---------------- idx table: clip(bucket(delta)+256, 0, 511) -----------------
__global__ void build_idx_kernel() {
    int t = blockIdx.x * blockDim.x + threadIdx.x;
    if (t >= 2047) return;
    int rel = t - 1023;
    int bucket;
    if (rel > -128 && rel < 128) {
        bucket = rel;
    } else {
        double abs_pos = fabs((double)rel);
        if (abs_pos <= 128.0) {
            bucket = rel;
        } else {
            int sgn = (rel > 0) - (rel < 0);
            double lp = ceil(log(abs_pos / 128.0) / log(511.0 / 128.0) * 127.0) + 128.0;
            bucket = (int)lp * sgn;
        }
    }
    int i1 = bucket + 256;
    i1 = i1 < 0 ? 0 : (i1 > 511 ? 511 : i1);
    g_idx[t] = i1;
}

// ---------------- fp32 -> fp16 convert ----------------------------------------
__global__ void to_half_kernel(const float4* __restrict__ in, __half* __restrict__ out, int n4) {
    int i = blockIdx.x * blockDim.x + threadIdx.x;
    if (i >= n4) return;
    float4 v = in[i];
    __half2 a = __floats2half2_rn(v.x, v.y);
    __half2 b = __floats2half2_rn(v.z, v.w);
    uint2 st;
    st.x = *(uint32_t*)&a;
    st.y = *(uint32_t*)&b;
    *(uint2*)(out + 4 * i) = st;
}

__device__ __forceinline__ float to_tf32(float x) {
    float y;
    asm("cvt.rna.tf32.f32 %0, %1;" : "=f"(y) : "f"(x));
    return y;
}

__device__ __forceinline__ void mma_tf32(float (&d)[4],
                                         uint32_t a0, uint32_t a1, uint32_t a2, uint32_t a3,
                                         uint32_t b0, uint32_t b1) {
    asm volatile(
        "mma.sync.aligned.m16n8k8.row.col.f32.tf32.tf32.f32 "
        "{%0,%1,%2,%3}, {%4,%5,%6,%7}, {%8,%9}, {%0,%1,%2,%3};\n"
        : "+f"(d[0]), "+f"(d[1]), "+f"(d[2]), "+f"(d[3])
        : "r"(a0), "r"(a1), "r"(a2), "r"(a3), "r"(b0), "r"(b1));
}

__device__ __forceinline__ void mma_f16(float (&d)[4],
                                        uint32_t a0, uint32_t a1, uint32_t a2, uint32_t a3,
                                        uint32_t b0, uint32_t b1) {
    asm volatile(
        "mma.sync.aligned.m16n8k16.row.col.f32.f16.f16.f32 "
        "{%0,%1,%2,%3}, {%4,%5,%6,%7}, {%8,%9}, {%0,%1,%2,%3};\n"
        : "+f"(d[0]), "+f"(d[1]), "+f"(d[2]), "+f"(d[3])
        : "r"(a0), "r"(a1), "r"(a2), "r"(a3), "r"(b0), "r"(b1));
}

__device__ __forceinline__ void cpa16(uint32_t s, const void* g) {
    asm volatile("cp.async.cg.shared.global [%0], [%1], 16;\n" :: "r"(s), "l"(g));
}
#define CP_COMMIT() asm volatile("cp.async.commit_group;\n" ::: "memory")
#define CP_WAIT1()  asm volatile("cp.async.wait_group 1;\n" ::: "memory")

// ============================================================================
// NT tf32 GEMM (champion, unchanged): used for K=64 GEMMs only.
// EPI 3: scores -> fp16 g_Ph, masked -> -60000
// EPI 5: merged c2p/p2c -> fp16 tables
// ============================================================================
template<int MT, int BN, int EPI>
__global__ __launch_bounds__(256) void mm_nt(
    const float* __restrict__ A, int lda, long long sAz,
    const float* __restrict__ B0, const float* __restrict__ B1, const float* __restrict__ B2,
    int ldb, long long sBz, int mods,
    void* __restrict__ O0, void* __restrict__ O1, void* __restrict__ O2,
    void* __restrict__ O3, void* __restrict__ O4,
    int ldc, long long sCz, int K,
    const float* __restrict__ bias0, const float* __restrict__ bias1, const float* __restrict__ bias2,
    const float* __restrict__ resid, int srows)
{
    constexpr int BM = 32 * MT;
    constexpr int WN8 = BN / 32;
    constexpr int AF = BM * 32;
    constexpr int BF = BN * 32;
    extern __shared__ float sm[];
    float* sA = sm;
    float* sB = sm + STAGES * AF;

    const int z = blockIdx.z;
    int zeff = z;
    const float* Bsel = B0; void* Osel = O0;
    const float* Asel = A;
    if (EPI == 5) {
        zeff = z & 31;
        if (z >= 32) { Asel = B1; Bsel = B2; Osel = O1; }
    }
    const float* Ag = Asel + (size_t)((mods & 2) ? (zeff & 15) : zeff) * sAz;
    const float* Bg = Bsel + (size_t)(((mods & 1) || EPI == 5) ? (zeff & 15) : zeff) * sBz;

    const int tid = threadIdx.x;
    const int m0 = blockIdx.y * BM, n0 = blockIdx.x * BN;
    const uint32_t sA_u = (uint32_t)__cvta_generic_to_shared(sA);
    const uint32_t sB_u = (uint32_t)__cvta_generic_to_shared(sB);

    const int wid = tid >> 5, lane = tid & 31;
    const int wm = wid & 1, wn = wid >> 1;
    const int r = lane >> 2, cq = lane & 3;

    float acc[MT][WN8][4];
    #pragma unroll
    for (int mt = 0; mt < MT; mt++)
        #pragma unroll
        for (int nt = 0; nt < WN8; nt++)
            #pragma unroll
            for (int q = 0; q < 4; q++) acc[mt][nt][q] = 0.f;

    auto loadStage = [&](int st, int k0) {
        #pragma unroll
        for (int i = 0; i < MT; i++) {
            int id = tid + i * 256;
            int row = id >> 3, c = id & 7;
            uint32_t dst = sA_u + (uint32_t)((st * AF + row * 32 + ((c ^ (row & 7)) << 2)) << 2);
            cpa16(dst, Ag + (size_t)(m0 + row) * lda + k0 + (c << 2));
        }
        #pragma unroll
        for (int i = 0; i < BN / 32; i++) {
            int id = tid + i * 256;
            int row = id >> 3, c = id & 7;
            uint32_t dst = sB_u + (uint32_t)((st * BF + row * 32 + ((c ^ (row & 7)) << 2)) << 2);
            cpa16(dst, Bg + (size_t)(n0 + row) * ldb + k0 + (c << 2));
        }
    };

    const int nk = K >> 5;
    loadStage(0, 0);  CP_COMMIT();
    loadStage(1, 32); CP_COMMIT();

    for (int it = 0; it < nk; it++) {
        CP_WAIT1();
        __syncthreads();
        int nxt = it + 2;
        if (nxt < nk) loadStage(nxt % STAGES, nxt * 32);
        CP_COMMIT();

        const float* a = sA + (it % STAGES) * AF;
        const float* b = sB + (it % STAGES) * BF;
        #pragma unroll
        for (int ks = 0; ks < 4; ks++) {
            uint32_t af0[MT], af1[MT], af2[MT], af3[MT];
            #pragma unroll
            for (int mt = 0; mt < MT; mt++) {
                int R = wm * (16 * MT) + mt * 16 + r;
                int r7 = R & 7;
                int lo = ((2 * ks) ^ r7) << 2, hi = ((2 * ks + 1) ^ r7) << 2;
                af0[mt] = __float_as_uint(a[R * 32 + lo + cq]);
                af2[mt] = __float_as_uint(a[R * 32 + hi + cq]);
                af1[mt] = __float_as_uint(a[(R + 8) * 32 + lo + cq]);
                af3[mt] = __float_as_uint(a[(R + 8) * 32 + hi + cq]);
            }
            #pragma unroll
            for (int nt = 0; nt < WN8; nt++) {
                int Nn = wn * WN8 * 8 + nt * 8 + r;
                int n7 = Nn & 7;
                int lo = ((2 * ks) ^ n7) << 2, hi = ((2 * ks + 1) ^ n7) << 2;
                uint32_t b0 = __float_as_uint(b[Nn * 32 + lo + cq]);
                uint32_t b1 = __float_as_uint(b[Nn * 32 + hi + cq]);
                #pragma unroll
                for (int mt = 0; mt < MT; mt++)
                    mma_tf32(acc[mt][nt], af0[mt], af1[mt], af2[mt], af3[mt], b0, b1);
            }
        }
        __syncthreads();
    }

    int* sidx = (int*)sm;
    if (EPI == 3) {
        int base = m0 - n0 - 127 + 1023;
        if (tid < 255) sidx[tid] = g_idx[base + tid];
        __syncthreads();
    }
    const int doff = (EPI == 3) ? (127 - (m0 - n0)) : 0;

    #pragma unroll
    for (int mt = 0; mt < MT; mt++) {
        #pragma unroll
        for (int e = 0; e < 2; e++) {
            int gm = m0 + wm * (16 * MT) + mt * 16 + r + e * 8;
            #pragma unroll
            for (int nt = 0; nt < WN8; nt++) {
                int gn = n0 + wn * WN8 * 8 + nt * 8 + 2 * cq;
                float v0 = acc[mt][nt][e * 2 + 0];
                float v1 = acc[mt][nt][e * 2 + 1];
                if (EPI == 5) {
                    __half* Cz = (__half*)Osel + (size_t)zeff * sCz;
                    __half2 o = __floats2half2_rn(v0, v1);
                    *(__half2*)(Cz + (size_t)gm * ldc + gn) = o;
                } else if (EPI == 3) {
                    __half* Cz = (__half*)Osel + (size_t)zeff * sCz;
                    int id0 = sidx[gm - gn + doff];
                    int id1 = sidx[gm - gn - 1 + doff];
                    size_t cb = ((size_t)z * SS + gm) * PP;
                    const int* amr = (const int*)resid + ((size_t)((z >> 4) * SS + gm)) * SS;
                    int2 mk = *(const int2*)(amr + gn);
                    float o0 = mk.x ? (v0 + __half2float(g_C2Ph[cb + id0])
                                       + __half2float(g_P2Ch[((size_t)z * SS + gn) * PP + id0]))
                                      * INV_SCALE
                                    : -60000.0f;
                    float o1 = mk.y ? (v1 + __half2float(g_C2Ph[cb + id1])
                                       + __half2float(g_P2Ch[((size_t)z * SS + gn + 1) * PP + id1]))
                                      * INV_SCALE
                                    : -60000.0f;
                    __half2 o = __floats2half2_rn(o0, o1);
                    *(__half2*)(Cz + (size_t)gm * ldc + gn) = o;
                }
            }
        }
    }
}

// ============================================================================
// NT fp16 GEMM (f32 accum), 3-stage cp.async, 16B-chunk XOR swizzle, k-tile 64.
// Used for K=1024 GEMMs (nk=16 -> healthy pipeline).
// EPI 1: merged qkv+pos head-major scatter + bias -> fp32 (z 0..4; hextra = rel)
// EPI 2: +bias+resid (fextra) -> fp32 O
// ============================================================================
template<int MT, int BN, int EPI>
__global__ __launch_bounds__(256) void mm_h(
    const __half* __restrict__ A, int lda, long long sAz,
    const __half* __restrict__ B0, const __half* __restrict__ B1, const __half* __restrict__ B2,
    int ldb, long long sBz,
    void* __restrict__ O0, void* __restrict__ O1, void* __restrict__ O2,
    void* __restrict__ O3, void* __restrict__ O4,
    int ldc, int K,
    const float* __restrict__ bias0, const float* __restrict__ bias1, const float* __restrict__ bias2,
    const float* __restrict__ fextra, const __half* __restrict__ hextra,
    int srows)
{
    constexpr int BM = 32 * MT;
    constexpr int WN8 = BN / 32;
    constexpr int AF = BM * 64;
    constexpr int BF = BN * 64;
    extern __shared__ __half hsm[];
    __half* sA = hsm;
    __half* sB = hsm + STAGES * AF;

    const int z = blockIdx.z;
    int srows_ = srows;
    const __half* Bsel = B0; const float* bias = bias0; void* Osel = O0;
    const __half* Asel = A;
    if (EPI == 1) {
        if (z == 1)      { Bsel = B1; bias = bias1; Osel = O1; }
        else if (z == 2) { Bsel = B2; bias = bias2; Osel = O2; }
        else if (z == 3) { Bsel = B1; bias = bias1; Osel = O3; Asel = hextra; srows_ = PP; }
        else if (z == 4) { Bsel = B0; bias = bias0; Osel = O4; Asel = hextra; srows_ = PP; }
        if (z >= 3 && blockIdx.y >= 4) return;
    }
    const __half* Ag = Asel;
    const __half* Bg = Bsel;

    const int tid = threadIdx.x;
    const int m0 = blockIdx.y * BM, n0 = blockIdx.x * BN;
    const uint32_t sA_u = (uint32_t)__cvta_generic_to_shared(sA);
    const uint32_t sB_u = (uint32_t)__cvta_generic_to_shared(sB);

    const int wid = tid >> 5, lane = tid & 31;
    const int wm = wid & 1, wn = wid >> 1;
    const int r = lane >> 2, cq = lane & 3;

    float acc[MT][WN8][4];
    #pragma unroll
    for (int mt = 0; mt < MT; mt++)
        #pragma unroll
        for (int nt = 0; nt < WN8; nt++)
            #pragma unroll
            for (int q = 0; q < 4; q++) acc[mt][nt][q] = 0.f;

    auto loadStage = [&](int st, int k0) {
        #pragma unroll
        for (int i = 0; i < MT; i++) {
            int id = tid + i * 256;
            int row = id >> 3, c = id & 7;
            uint32_t dst = sA_u + (uint32_t)((st * AF + row * 64 + ((c ^ (row & 7)) << 3)) << 1);
            cpa16(dst, Ag + (size_t)(m0 + row) * lda + k0 + (c << 3));
        }
        #pragma unroll
        for (int i = 0; i < BN / 32; i++) {
            int id = tid + i * 256;
            int row = id >> 3, c = id & 7;
            uint32_t dst = sB_u + (uint32_t)((st * BF + row * 64 + ((c ^ (row & 7)) << 3)) << 1);
            cpa16(dst, Bg + (size_t)(n0 + row) * ldb + k0 + (c << 3));
        }
    };

    const int nk = K >> 6;
    loadStage(0, 0);  CP_COMMIT();
    loadStage(1, 64); CP_COMMIT();

    for (int it = 0; it < nk; it++) {
        CP_WAIT1();
        __syncthreads();
        int nxt = it + 2;
        if (nxt < nk) loadStage(nxt % STAGES, nxt * 64);
        CP_COMMIT();

        const __half* a = sA + (it % STAGES) * AF;
        const __half* b = sB + (it % STAGES) * BF;
        #pragma unroll
        for (int ks = 0; ks < 4; ks++) {
            uint32_t af0[MT], af1[MT], af2[MT], af3[MT];
            #pragma unroll
            for (int mt = 0; mt < MT; mt++) {
                int R = wm * (16 * MT) + mt * 16 + r;
                int r7 = R & 7;
                int lo = ((2 * ks) ^ r7) << 3, hi = ((2 * ks + 1) ^ r7) << 3;
                af0[mt] = *(const uint32_t*)&a[R * 64 + lo + 2 * cq];
                af2[mt] = *(const uint32_t*)&a[R * 64 + hi + 2 * cq];
                af1[mt] = *(const uint32_t*)&a[(R + 8) * 64 + lo + 2 * cq];
                af3[mt] = *(const uint32_t*)&a[(R + 8) * 64 + hi + 2 * cq];
            }
            #pragma unroll
            for (int nt = 0; nt < WN8; nt++) {
                int Nn = wn * WN8 * 8 + nt * 8 + r;
                int n7 = Nn & 7;
                uint32_t b0 = *(const uint32_t*)&b[Nn * 64 + (((2 * ks) ^ n7) << 3) + 2 * cq];
                uint32_t b1 = *(const uint32_t*)&b[Nn * 64 + (((2 * ks + 1) ^ n7) << 3) + 2 * cq];
                #pragma unroll
                for (int mt = 0; mt < MT; mt++)
                    mma_f16(acc[mt][nt], af0[mt], af1[mt], af2[mt], af3[mt], b0, b1);
            }
        }
        __syncthreads();
    }

    #pragma unroll
    for (int mt = 0; mt < MT; mt++) {
        #pragma unroll
        for (int e = 0; e < 2; e++) {
            int gm = m0 + wm * (16 * MT) + mt * 16 + r + e * 8;
            #pragma unroll
            for (int nt = 0; nt < WN8; nt++) {
                int gn = n0 + wn * WN8 * 8 + nt * 8 + 2 * cq;
                float v0 = acc[mt][nt][e * 2 + 0];
                float v1 = acc[mt][nt][e * 2 + 1];
                if (EPI == 1) {
                    int h = gn >> 6, d = gn & 63;
                    int b = gm / srows_, s = gm % srows_;
                    float2 o = {v0 + bias[gn], v1 + bias[gn + 1]};
                    *(float2*)((float*)Osel + ((((size_t)b * HH + h) * srows_ + s) << 6) + d) = o;
                } else { // EPI == 2
                    size_t ad = (size_t)gm * ldc + gn;
                    float2 rr = *(const float2*)(fextra + ad);
                    float2 o = {v0 + bias[gn] + rr.x, v1 + bias[gn + 1] + rr.y};
                    *(float2*)((float*)Osel + ad) = o;
                }
            }
        }
    }
}

// -------- weight transpose -> fp16: Wth[n][k] = (half)W[k][n] ----------------
__global__ void transpose_w(const float* __restrict__ W0, const float* __restrict__ W1,
                            const float* __restrict__ W2, const float* __restrict__ W3)
{
    __shared__ float t[32][33];
    int zz = blockIdx.z;
    const float* W = zz == 0 ? W0 : zz == 1 ? W1 : zz == 2 ? W2 : W3;
    __half* Tz = g_Wth + (size_t)zz * DMODEL * DMODEL;
    int x = blockIdx.x * 32 + threadIdx.x;
    int y0 = blockIdx.y * 32;
    #pragma unroll
    for (int i = threadIdx.y; i < 32; i += 8)
        t[i][threadIdx.x] = W[(size_t)(y0 + i) * DMODEL + x];
    __syncthreads();
    int xo = blockIdx.y * 32 + threadIdx.x;
    int yo0 = blockIdx.x * 32;
    #pragma unroll
    for (int i = threadIdx.y; i < 32; i += 8)
        Tz[(size_t)(yo0 + i) * DMODEL + xo] = __float2half(t[threadIdx.x][i]);
}

// -------- V transpose per head -> fp16: Vth[bh][d][s] = (half)V[bh][s][d] ----
__global__ void transpose_v()
{
    __shared__ float t[32][33];
    int bh = blockIdx.z;
    int s0 = blockIdx.x * 32, d0 = blockIdx.y * 32;
    const float* Vi = g_V + (size_t)bh * SS * DD;
    __half* Vo = g_Vth + (size_t)bh * DD * SS;
    #pragma unroll
    for (int i = threadIdx.y; i < 32; i += 8)
        t[i][threadIdx.x] = Vi[(size_t)(s0 + i) * DD + d0 + threadIdx.x];
    __syncthreads();
    #pragma unroll
    for (int i = threadIdx.y; i < 32; i += 8)
        Vo[(size_t)(d0 + i) * SS + s0 + threadIdx.x] = __float2half(t[threadIdx.x][i]);
}

// ------- maskless softmax, fp16 in place (sentinel -60000 -> prob 0) ---------
__global__ __launch_bounds__(256) void softmax_kernel()
{
    __shared__ float redm[8];
    __shared__ float reds[8];
    int row = blockIdx.x;              // bh*S + q
    __half* srow = g_Ph + (size_t)row * SS;
    int t = threadIdx.x, lane = t & 31, wid = t >> 5;
    uint2 raw = *(const uint2*)(srow + 4 * t);
    __half2 ha = *(__half2*)&raw.x;
    __half2 hb = *(__half2*)&raw.y;
    float2 f0 = __half22float2(ha);
    float2 f1 = __half22float2(hb);
    float mx = fmaxf(fmaxf(f0.x, f0.y), fmaxf(f1.x, f1.y));
    #pragma unroll
    for (int o = 16; o; o >>= 1) mx = fmaxf(mx, __shfl_xor_sync(0xffffffffu, mx, o));
    if (lane == 0) redm[wid] = mx;
    __syncthreads();
    mx = redm[0];
    #pragma unroll
    for (int i = 1; i < 8; i++) mx = fmaxf(mx, redm[i]);
    float p0 = f0.x < -5.0e4f ? 0.f : __expf(f0.x - mx);
    float p1 = f0.y < -5.0e4f ? 0.f : __expf(f0.y - mx);
    float p2 = f1.x < -5.0e4f ? 0.f : __expf(f1.x - mx);
    float p3 = f1.y < -5.0e4f ? 0.f : __expf(f1.y - mx);
    float sm = p0 + p1 + p2 + p3;
    #pragma unroll
    for (int o = 16; o; o >>= 1) sm += __shfl_xor_sync(0xffffffffu, sm, o);
    if (lane == 0) reds[wid] = sm;
    __syncthreads();
    sm = reds[0];
    #pragma unroll
    for (int i = 1; i < 8; i++) sm += reds[i];
    float inv = sm > 0.f ? 1.f / sm : 0.f;
    __half2 h0 = __floats2half2_rn(p0 * inv, p1 * inv);
    __half2 h1 = __floats2half2_rn(p2 * inv, p3 * inv);
    uint2 st;
    st.x = *(uint32_t*)&h0;
    st.y = *(uint32_t*)&h1;
    *(uint2*)(srow + 4 * t) = st;
}

// ============================================================================
// PV fp16 mma: ctx(fp16) = P(fp16) @ V(fp16) per bh.  Block 64q x 64d.
// ============================================================================
#define PVH_AF 4096
#define PVH_BF 4096
#define PVH_SMEM (STAGES * (PVH_AF + PVH_BF) * 2)   // 49152 B

__global__ __launch_bounds__(256) void pv_h()
{
    extern __shared__ __half hsm[];
    __half* sA = hsm;
    __half* sB = hsm + STAGES * PVH_AF;

    const int bh = blockIdx.z, b = bh >> 4, h = bh & 15;
    const int q0 = blockIdx.y * 64;
    const int tid = threadIdx.x, wid = tid >> 5, lane = tid & 31;
    const int wm = wid & 1, wn = wid >> 1, r = lane >> 2, cq = lane & 3;

    const __half* Pg = g_Ph + (size_t)bh * SS * SS + (size_t)q0 * SS;
    const __half* Vg = g_Vth + (size_t)bh * DD * SS;
    const uint32_t sA_u = (uint32_t)__cvta_generic_to_shared(sA);
    const uint32_t sB_u = (uint32_t)__cvta_generic_to_shared(sB);

    float acc[2][2][4];
    #pragma unroll
    for (int mt = 0; mt < 2; mt++)
        #pragma unroll
        for (int nt = 0; nt < 2; nt++)
            #pragma unroll
            for (int q = 0; q < 4; q++) acc[mt][nt][q] = 0.f;

    auto loadStage = [&](int st, int k0) {
        #pragma unroll
        for (int i = 0; i < 2; i++) {
            int id = tid + i * 256;
            int row = id >> 3, c = id & 7;
            uint32_t dst = sA_u + (uint32_t)((st * PVH_AF + row * 64 + ((c ^ (row & 7)) << 3)) << 1);
            cpa16(dst, Pg + (size_t)row * SS + k0 + (c << 3));
        }
        #pragma unroll
        for (int i = 0; i < 2; i++) {
            int id = tid + i * 256;
            int row = id >> 3, c = id & 7;
            uint32_t dst = sB_u + (uint32_t)((st * PVH_BF + row * 64 + ((c ^ (row & 7)) << 3)) << 1);
            cpa16(dst, Vg + (size_t)row * SS + k0 + (c << 3));
        }
    };

    const int nk = SS / 64;
    loadStage(0, 0);  CP_COMMIT();
    loadStage(1, 64); CP_COMMIT();

    for (int it = 0; it < nk; it++) {
        CP_WAIT1();
        __syncthreads();
        int nxt = it + 2;
        if (nxt < nk) loadStage(nxt % STAGES, nxt * 64);
        CP_COMMIT();

        const __half* a = sA + (it % STAGES) * PVH_AF;
        const __half* bb = sB + (it % STAGES) * PVH_BF;
        #pragma unroll
        for (int ks = 0; ks < 4; ks++) {
            uint32_t af0[2], af1[2], af2[2], af3[2];
            #pragma unroll
            for (int mt = 0; mt < 2; mt++) {
                int R = wm * 32 + mt * 16 + r;
                int r7 = R & 7;
                int lo = ((2 * ks) ^ r7) << 3, hi = ((2 * ks + 1) ^ r7) << 3;
                af0[mt] = *(const uint32_t*)&a[R * 64 + lo + 2 * cq];
                af2[mt] = *(const uint32_t*)&a[R * 64 + hi + 2 * cq];
                af1[mt] = *(const uint32_t*)&a[(R + 8) * 64 + lo + 2 * cq];
                af3[mt] = *(const uint32_t*)&a[(R + 8) * 64 + hi + 2 * cq];
            }
            #pragma unroll
            for (int nt = 0; nt < 2; nt++) {
                int n = wn * 16 + nt * 8 + r;
                int n7 = n & 7;
                uint32_t b0 = *(const uint32_t*)&bb[n * 64 + (((2 * ks) ^ n7) << 3) + 2 * cq];
                uint32_t b1 = *(const uint32_t*)&bb[n * 64 + (((2 * ks + 1) ^ n7) << 3) + 2 * cq];
                #pragma unroll
                for (int mt = 0; mt < 2; mt++)
                    mma_f16(acc[mt][nt], af0[mt], af1[mt], af2[mt], af3[mt], b0, b1);
            }
        }
        __syncthreads();
    }

    // epilogue: write ctx fp16 [B,S,DM]
    #pragma unroll
    for (int mt = 0; mt < 2; mt++) {
        #pragma unroll
        for (int e = 0; e < 2; e++) {
            int gm = q0 + wm * 32 + mt * 16 + r + e * 8;
            #pragma unroll
            for (int nt = 0; nt < 2; nt++) {
                int d = wn * 16 + nt * 8 + 2 * cq;
                __half2 o = __floats2half2_rn(acc[mt][nt][e * 2 + 0], acc[mt][nt][e * 2 + 1]);
                *(__half2*)(g_ctxh + (size_t)(b * SS + gm) * DMODEL + h * DD + d) = o;
            }
        }
    }
}

// ---------------- layernorm of g_H, write to output --------------------------
__global__ __launch_bounds__(256) void ln_kernel(
    const float* __restrict__ lw, const float* __restrict__ lb,
    float* __restrict__ out)
{
    __shared__ float red[256];
    __shared__ float red2[256];
    int r = blockIdx.x, t = threadIdx.x;
    const float* x = g_H + (size_t)r * DMODEL;
    float s = 0.f, s2 = 0.f;
    #pragma unroll
    for (int i = 0; i < 4; i++) {
        float v = x[t + i * 256];
        s += v; s2 += v * v;
    }
    red[t] = s; red2[t] = s2; __syncthreads();
    for (int st = 128; st; st >>= 1) {
        if (t < st) { red[t] += red[t + st]; red2[t] += red2[t + st]; }
        __syncthreads();
    }
    float mu = red[0] * (1.f / DMODEL);
    float var = red2[0] * (1.f / DMODEL) - mu * mu;
    float inv = rsqrtf(var + 1e-7f);
    #pragma unroll
    for (int i = 0; i < 4; i++) {
        int c = t + i * 256;
        out[(size_t)r * DMODEL + c] = (x[c] - mu) * inv * lw[c] + lb[c];
    }
}

// ---------------- launch ------------------------------------------------------
extern "C" void kernel_launch(void* const* d_in, const int* in_sizes, int n_in,
                              void* d_out, int out_size)
{
    const float* hs  = (const float*)d_in[0];
    const float* rel = (const float*)d_in[1];
    const float* Wq  = (const float*)d_in[2];  const float* bq = (const float*)d_in[3];
    const float* Wk  = (const float*)d_in[4];  const float* bk = (const float*)d_in[5];
    const float* Wv  = (const float*)d_in[6];  const float* bv = (const float*)d_in[7];
    const float* Wo  = (const float*)d_in[8];  const float* bo = (const float*)d_in[9];
    const float* lw  = (const float*)d_in[10]; const float* lb = (const float*)d_in[11];
    const int*   am  = (const int*)d_in[12];
    float* out = (float*)d_out;

    float *Q_, *K_, *V_, *PK_, *PQ_, *Hb_;
    __half *HSH_, *RELH_, *WTH_, *C2PH_, *P2CH_, *PH_, *CTXH_;
    cudaGetSymbolAddress((void**)&HSH_,  g_hsh);
    cudaGetSymbolAddress((void**)&RELH_, g_relh);
    cudaGetSymbolAddress((void**)&WTH_,  g_Wth);
    cudaGetSymbolAddress((void**)&Q_,    g_Q);
    cudaGetSymbolAddress((void**)&K_,    g_K);
    cudaGetSymbolAddress((void**)&V_,    g_V);
    cudaGetSymbolAddress((void**)&PK_,   g_posK);
    cudaGetSymbolAddress((void**)&PQ_,   g_posQ);
    cudaGetSymbolAddress((void**)&C2PH_, g_C2Ph);
    cudaGetSymbolAddress((void**)&P2CH_, g_P2Ch);
    cudaGetSymbolAddress((void**)&PH_,   g_Ph);
    cudaGetSymbolAddress((void**)&CTXH_, g_ctxh);
    cudaGetSymbolAddress((void**)&Hb_,   g_H);

    __half* WTH0 = WTH_;
    __half* WTH1 = WTH_ + (size_t)1 * DMODEL * DMODEL;
    __half* WTH2 = WTH_ + (size_t)2 * DMODEL * DMODEL;
    __half* WTH3 = WTH_ + (size_t)3 * DMODEL * DMODEL;

    const int SM4_128 = STAGES * (128 * 32 + 128 * 32) * 4;   // 98304 (tf32)
    const int SMH4    = STAGES * (128 * 64 + 128 * 64) * 2;   // 98304 (fp16)
    const int SMH2    = STAGES * (64 * 64 + 128 * 64) * 2;    // 73728
    cudaFuncSetAttribute(mm_nt<4,128,5>, cudaFuncAttributeMaxDynamicSharedMemorySize, SM4_128);
    cudaFuncSetAttribute(mm_nt<4,128,3>, cudaFuncAttributeMaxDynamicSharedMemorySize, SM4_128);
    cudaFuncSetAttribute(mm_h<4,128,1>,  cudaFuncAttributeMaxDynamicSharedMemorySize, SMH4);
    cudaFuncSetAttribute(mm_h<2,128,2>,  cudaFuncAttributeMaxDynamicSharedMemorySize, SMH2);
    cudaFuncSetAttribute(pv_h, cudaFuncAttributeMaxDynamicSharedMemorySize, PVH_SMEM);

    build_idx_kernel<<<8, 256>>>();
    to_half_kernel<<<2048, 256>>>((const float4*)hs, HSH_, BB*SS*DMODEL/4);
    to_half_kernel<<<512, 256>>>((const float4*)rel, RELH_, PP*DMODEL/4);
    transpose_w<<<dim3(32, 32, 4), dim3(32, 8)>>>(Wq, Wk, Wv, Wo);

    // QKV + position projections (fp16 mma, fp32 out), one launch
    mm_h<4,128,1><<<dim3(8,16,5),256,SMH4>>>(
        HSH_,1024,0, WTH0,WTH1,WTH2, 1024,0,
        Q_,K_,V_,PK_,PQ_, 0, 1024, bq,bk,bv, nullptr, RELH_, SS);
    transpose_v<<<dim3(32, 2, 32), dim3(32, 8)>>>();

    // merged disentangled tables (tf32, fp16 out): z<32 -> C2P ; z>=32 -> P2C
    mm_nt<4,128,5><<<dim3(4,8,64),256,SM4_128>>>(
        Q_,64,(long long)SS*DD, PK_,K_,PQ_, 64,(long long)PP*DD,0,
        C2PH_,P2CH_,nullptr,nullptr,nullptr, PP,(long long)SS*PP, 64,
        nullptr,nullptr,nullptr, nullptr, 0);

    // scores (tf32) = (Q K^T + gathers)*scale -> fp16, masked -> -60000
    mm_nt<4,128,3><<<dim3(8,8,32),256,SM4_128>>>(
        Q_,64,(long long)SS*DD, K_,nullptr,nullptr, 64,(long long)SS*DD,0,
        PH_,nullptr,nullptr,nullptr,nullptr, SS,(long long)SS*SS, 64,
        nullptr,nullptr,nullptr, (const float*)am, 0);
    softmax_kernel<<<BH*SS, 256>>>();

    // ctx(fp16) = probs(fp16) @ V(fp16)
    pv_h<<<dim3(1, 16, 32), 256, PVH_SMEM>>>();

    // output projection (fp16 mma) + residual -> fp32 H, then layernorm
    mm_h<2,128,2><<<dim3(8,32,1),256,SMH2>>>(
        CTXH_,1024,0, WTH3,nullptr,nullptr, 1024,0,
        Hb_,nullptr,nullptr,nullptr,nullptr, 1024, 1024,
        bo,nullptr,nullptr, hs,nullptr, 0);
    ln_kernel<<<BB*SS, 256>>>(lw, lb, out);
}